// round 13
// baseline (speedup 1.0000x reference)
#include <cuda_runtime.h>
#include <cuda_bf16.h>
#include <math.h>
#include <stdint.h>

// Problem constants
#define BATCH 4
#define CDIM  512
#define TDIM  2048
#define NCB   4096
#define HH    4
// Physical split storage: [hi|lo] = 1024 bf16 = 2048 B per row.
// Logical K = 1536: products Ah*Bh + Al*Bh + Ah*Bl per 64-col ci-group.
#define KPHYS 1024
#define ROWB  2048
#define CSCALE 0.04419417382415922f   // 1/(sqrt(128)*sqrt(4))

#define NBLOCKS (NCB / 128)        // 32 partial-argmax slices

// ---------------- scratch (device globals; no runtime allocation) -----------
__device__ __nv_bfloat16 g_AcbS[(size_t)NCB * KPHYS];          // cb split [hi|lo]
__device__ __nv_bfloat16 g_HsS [(size_t)BATCH * TDIM * KPHYS]; // hs^T split [hi|lo]
__device__ __nv_bfloat16 g_WTS [3][(size_t)CDIM * KPHYS];      // Wq,Wk,Wv^T [hi|lo]
__device__ __nv_bfloat16 g_KpS[(size_t)NCB * KPHYS];           // K' split [hi|lo]
__device__ __nv_bfloat16 g_QgS[(size_t)BATCH * TDIM * KPHYS];  // Qg split [hi|lo]
__device__ float g_V [(size_t)NCB * CDIM];
__device__ float g_cg[(size_t)BATCH * TDIM * HH];   // includes bias
__device__ int   g_idx[(size_t)BATCH * TDIM];
__device__ float g_pmax[NBLOCKS * BATCH * TDIM];
__device__ int   g_pidx[NBLOCKS * BATCH * TDIM];

// ======================= helpers ============================================
#define SMEM_SWIZZLE_128B(off) ((off) ^ (((off) >> 3) & 0x70))
#define CP_ASYNC16(dst, src) \
    asm volatile("cp.async.cg.shared.global [%0], [%1], 16;" :: "r"(dst), "l"(src))
#define CP_ASYNC_COMMIT() asm volatile("cp.async.commit_group;" ::: "memory")

__device__ __forceinline__ uint32_t smem_to_u32(const void* p) {
    uint32_t a;
    asm("{ .reg .u64 t; cvta.to.shared.u64 t, %1; cvt.u32.u64 %0, t; }"
        : "=r"(a) : "l"(p));
    return a;
}
__device__ __forceinline__ void ldsm_x4(uint32_t& r0, uint32_t& r1, uint32_t& r2,
                                        uint32_t& r3, uint32_t addr) {
    asm volatile("ldmatrix.sync.aligned.m8n8.x4.shared.b16 {%0,%1,%2,%3}, [%4];"
                 : "=r"(r0), "=r"(r1), "=r"(r2), "=r"(r3) : "r"(addr));
}
__device__ __forceinline__ void mma16816(float* c, uint32_t a0, uint32_t a1,
                                         uint32_t a2, uint32_t a3,
                                         uint32_t b0, uint32_t b1) {
    asm volatile(
        "mma.sync.aligned.m16n8k16.row.col.f32.bf16.bf16.f32 "
        "{%0,%1,%2,%3}, {%4,%5,%6,%7}, {%8,%9}, {%0,%1,%2,%3};"
        : "+f"(c[0]), "+f"(c[1]), "+f"(c[2]), "+f"(c[3])
        : "r"(a0), "r"(a1), "r"(a2), "r"(a3), "r"(b0), "r"(b1));
}
__device__ __forceinline__ void split2bf(float v0, float v1, unsigned& hu, unsigned& lu) {
    __nv_bfloat16 h0 = __float2bfloat16(v0), h1 = __float2bfloat16(v1);
    float r0 = v0 - __bfloat162float(h0), r1 = v1 - __bfloat162float(h1);
    __nv_bfloat16 l0 = __float2bfloat16(r0), l1 = __float2bfloat16(r1);
    __nv_bfloat162 ph = __halves2bfloat162(h0, h1);
    __nv_bfloat162 pl = __halves2bfloat162(l0, l1);
    hu = *reinterpret_cast<unsigned*>(&ph);
    lu = *reinterpret_cast<unsigned*>(&pl);
}
__device__ __forceinline__ void split1bf(float v, __nv_bfloat16& h, __nv_bfloat16& l) {
    h = __float2bfloat16(v);
    l = __float2bfloat16(v - __bfloat162float(h));
}

// ====== canonical logical-K=1536 bf16 mma core with tile reuse ==============
// (R9 core: 16 loads, 24 MMA chunks, 2 syncs/group)
#define GEMM_STAGE  32768                    // A 16KB + B 16KB
#define GEMM_SMEM   (3 * GEMM_STAGE)         // 98304

__device__ __forceinline__ void gemm1536_core(const char* Abase, const char* Bbase,
                                              uint32_t sb, int tid,
                                              float (&acc)[16][4]) {
    const int lane = tid & 31;
    const int wid  = tid >> 5;
    const int wm = wid & 1, wn = wid >> 1;

    #define GLOAD(j) do { \
        uint32_t _as = sb + ((j) % 3) * GEMM_STAGE; \
        uint32_t _bs = _as + 16384; \
        size_t _ko = (size_t)(((j) & 1) ? 8 + ((j) >> 1) : ((j) >> 1)) * 128; \
        _Pragma("unroll") \
        for (int _i = 0; _i < 4; _i++) { \
            int _u = tid + _i * 256; \
            int _r = _u >> 3, _c16 = (_u & 7) * 16; \
            CP_ASYNC16(_as + SMEM_SWIZZLE_128B(_r * 128 + _c16), \
                       Abase + (size_t)_r * ROWB + _ko + _c16); \
        } \
        _Pragma("unroll") \
        for (int _i = 0; _i < 4; _i++) { \
            int _u = tid + _i * 256; \
            int _r = _u >> 3, _c16 = (_u & 7) * 16; \
            CP_ASYNC16(_bs + SMEM_SWIZZLE_128B(_r * 128 + _c16), \
                       Bbase + (size_t)_r * ROWB + _ko + _c16); \
        } \
        CP_ASYNC_COMMIT(); \
    } while (0)

    #define MMA_CHUNK(Astage, Bstage) do { \
        uint32_t _As = sb + (Astage) * GEMM_STAGE; \
        uint32_t _Bs = sb + (Bstage) * GEMM_STAGE + 16384; \
        _Pragma("unroll") \
        for (int kk = 0; kk < 4; kk++) { \
            uint32_t a[4][4]; \
            _Pragma("unroll") \
            for (int mi = 0; mi < 4; mi++) { \
                int row = wm * 64 + mi * 16 + (lane & 15); \
                int u   = kk * 2 + (lane >> 4); \
                ldsm_x4(a[mi][0], a[mi][1], a[mi][2], a[mi][3], \
                        _As + row * 128 + ((u ^ (row & 7)) << 4)); \
            } \
            uint32_t bf[2][4]; \
            _Pragma("unroll") \
            for (int nf = 0; nf < 2; nf++) { \
                int row = wn * 32 + nf * 16 + ((lane >> 4) << 3) + (lane & 7); \
                int u   = kk * 2 + ((lane >> 3) & 1); \
                ldsm_x4(bf[nf][0], bf[nf][1], bf[nf][2], bf[nf][3], \
                        _Bs + row * 128 + ((u ^ (row & 7)) << 4)); \
            } \
            _Pragma("unroll") \
            for (int mi = 0; mi < 4; mi++) \
                _Pragma("unroll") \
                for (int nj = 0; nj < 4; nj++) \
                    mma16816(acc[mi * 4 + nj], \
                             a[mi][0], a[mi][1], a[mi][2], a[mi][3], \
                             bf[nj >> 1][(nj & 1) * 2], bf[nj >> 1][(nj & 1) * 2 + 1]); \
        } \
    } while (0)

    GLOAD(0); GLOAD(1); GLOAD(2);

    #pragma unroll
    for (int g = 0; g < 8; g++) {
        const int sA = (2 * g) % 3;
        const int sB = (2 * g + 1) % 3;

        if (g == 0) asm volatile("cp.async.wait_group 2;" ::: "memory");
        else        asm volatile("cp.async.wait_group 0;" ::: "memory");
        __syncthreads();
        if (g >= 1) {
            GLOAD(2 * g + 1);
            if (2 * g + 2 <= 15) GLOAD(2 * g + 2);
        }
        MMA_CHUNK(sA, sA);

        if (g == 7) asm volatile("cp.async.wait_group 0;" ::: "memory");
        else        asm volatile("cp.async.wait_group 1;" ::: "memory");
        __syncthreads();
        MMA_CHUNK(sB, sA);

        MMA_CHUNK(sA, sB);
    }
    #undef GLOAD
    #undef MMA_CHUNK
}

// ===================== merged prep kernel ===================================
// bx < 2048            : cb split
// 2048 <= bx < 2816    : Wq/Wk/Wv transpose-split
// 2816 <= bx < 3072    : hidden transpose-split + fused head gates
__global__ void prep_all_kernel(const float* __restrict__ cb,
                                const float* __restrict__ Wq,
                                const float* __restrict__ Wk,
                                const float* __restrict__ Wv,
                                const float* __restrict__ hidden,
                                const float* __restrict__ Wp,
                                const float* __restrict__ bp) {
    __shared__ float tile[32][33];
    __shared__ float sWp[CDIM * HH];
    int bx = blockIdx.x;
    if (bx < 2048) {
        int idx = bx * 256 + threadIdx.x;
        int n  = idx >> 7;
        int c4 = (idx & 127) * 4;
        float4 v = *(const float4*)(cb + (size_t)n * CDIM + c4);
        unsigned h0, l0, h1, l1;
        split2bf(v.x, v.y, h0, l0);
        split2bf(v.z, v.w, h1, l1);
        __nv_bfloat16* op = g_AcbS + (size_t)n * KPHYS + c4;
        *(uint2*)(op)       = make_uint2(h0, h1);
        *(uint2*)(op + 512) = make_uint2(l0, l1);
    } else if (bx < 2816) {
        int bid = bx - 2048;          // 0..767
        int z   = bid >> 8;           // 0..2
        int rem = bid & 255;
        int ci0 = (rem >> 4) * 32, c0 = (rem & 15) * 32;
        const float* W = (z == 0) ? Wq : (z == 1) ? Wk : Wv;
        int tx = threadIdx.x & 31, ty = threadIdx.x >> 5;
        #pragma unroll
        for (int k = 0; k < 4; k++)
            tile[ty + 8 * k][tx] = W[(size_t)(ci0 + ty + 8 * k) * CDIM + c0 + tx];
        __syncthreads();
        __nv_bfloat16* base = g_WTS[z];
        #pragma unroll
        for (int k = 0; k < 4; k++) {
            int c = c0 + ty + 8 * k;
            float v = tile[tx][ty + 8 * k];
            __nv_bfloat16 h, l; split1bf(v, h, l);
            __nv_bfloat16* op = base + (size_t)c * KPHYS + ci0 + tx;
            op[0] = h; op[512] = l;
        }
    } else {
        int r  = bx - 2816;           // 0..255
        int b  = r >> 6;
        int t0 = (r & 63) * 32;
        int tx = threadIdx.x & 31, ty = threadIdx.x >> 5;
        const float* hp = hidden + (size_t)b * CDIM * TDIM;

        #pragma unroll
        for (int i = 0; i < 8; i++)
            sWp[threadIdx.x + i * 256] = Wp[threadIdx.x + i * 256];

        float cgacc = 0.f;
        int tl = threadIdx.x >> 2, hh = threadIdx.x & 3;

        for (int ci0 = 0; ci0 < CDIM; ci0 += 32) {
            __syncthreads();
            #pragma unroll
            for (int k = 0; k < 4; k++)
                tile[ty + 8 * k][tx] = hp[(size_t)(ci0 + ty + 8 * k) * TDIM + t0 + tx];
            __syncthreads();
            #pragma unroll
            for (int k = 0; k < 4; k++) {
                int t = t0 + ty + 8 * k;
                float v = tile[tx][ty + 8 * k];
                __nv_bfloat16 h, l; split1bf(v, h, l);
                __nv_bfloat16* op = g_HsS + ((size_t)b * TDIM + t) * KPHYS + ci0 + tx;
                op[0] = h; op[512] = l;
            }
            if (threadIdx.x < 128) {
                #pragma unroll 8
                for (int ci = 0; ci < 32; ci++)
                    cgacc += tile[ci][tl] * sWp[(ci0 + ci) * 4 + hh];
            }
        }
        if (threadIdx.x < 128) {
            int bt = b * TDIM + t0 + tl;
            g_cg[(size_t)bt * 4 + hh] = cgacc + bp[hh];
        }
    }
}

// ===================== merged projection GEMMs (tensor) =====================
__global__ __launch_bounds__(256, 2)
void gemm_proj_all(const float* __restrict__ bq, const float* __restrict__ bk,
                   const float* __restrict__ bv) {
    extern __shared__ __align__(1024) char smem[];
    const int tid = threadIdx.x;
    const int lane = tid & 31, wid = tid >> 5;
    const int wm = wid & 1, wn = wid >> 1;
    const int y = blockIdx.y;
    const int cBase = blockIdx.x * 128;
    const uint32_t sb = smem_to_u32(smem);

    const char* Abase;
    const char* Bbase;
    int rBase;
    int mode;           // 0=K', 1=V, 2=Qg
    if (y < 32)       { mode = 0; rBase = y * 128;
                        Abase = (const char*)(g_AcbS + (size_t)rBase * KPHYS);
                        Bbase = (const char*)(g_WTS[1] + (size_t)cBase * KPHYS); }
    else if (y < 64)  { mode = 1; rBase = (y - 32) * 128;
                        Abase = (const char*)(g_AcbS + (size_t)rBase * KPHYS);
                        Bbase = (const char*)(g_WTS[2] + (size_t)cBase * KPHYS); }
    else              { mode = 2; rBase = (y - 64) * 128;
                        Abase = (const char*)(g_HsS + (size_t)rBase * KPHYS);
                        Bbase = (const char*)(g_WTS[0] + (size_t)cBase * KPHYS); }

    float acc[16][4] = {};
    gemm1536_core(Abase, Bbase, sb, tid, acc);

    if (mode == 0) {
        #pragma unroll
        for (int mi = 0; mi < 4; mi++)
            #pragma unroll
            for (int nj = 0; nj < 4; nj++) {
                float* A = acc[mi * 4 + nj];
                int r  = wm * 64 + mi * 16 + (lane >> 2);
                int cc = cBase + wn * 32 + nj * 8 + 2 * (lane & 3);
                float b0 = bk[cc], b1 = bk[cc + 1];
                unsigned h, l;
                split2bf(A[0] + b0, A[1] + b1, h, l);
                __nv_bfloat16* op = g_KpS + (size_t)(rBase + r) * KPHYS + cc;
                *(unsigned*)(op) = h; *(unsigned*)(op + 512) = l;
                split2bf(A[2] + b0, A[3] + b1, h, l);
                op = g_KpS + (size_t)(rBase + r + 8) * KPHYS + cc;
                *(unsigned*)(op) = h; *(unsigned*)(op + 512) = l;
            }
    } else if (mode == 1) {
        #pragma unroll
        for (int mi = 0; mi < 4; mi++)
            #pragma unroll
            for (int nj = 0; nj < 4; nj++) {
                float* A = acc[mi * 4 + nj];
                int r  = wm * 64 + mi * 16 + (lane >> 2);
                int cc = cBase + wn * 32 + nj * 8 + 2 * (lane & 3);
                float b0 = bv[cc], b1 = bv[cc + 1];
                *(float2*)(g_V + (size_t)(rBase + r) * CDIM + cc) =
                    make_float2(A[0] + b0, A[1] + b1);
                *(float2*)(g_V + (size_t)(rBase + r + 8) * CDIM + cc) =
                    make_float2(A[2] + b0, A[3] + b1);
            }
    } else {
        const int h = blockIdx.x;
        #pragma unroll
        for (int mi = 0; mi < 4; mi++)
            #pragma unroll
            for (int nj = 0; nj < 4; nj++) {
                float* A = acc[mi * 4 + nj];
                int r  = wm * 64 + mi * 16 + (lane >> 2);
                int cc = cBase + wn * 32 + nj * 8 + 2 * (lane & 3);
                float b0 = bq[cc], b1 = bq[cc + 1];
                int bt0 = rBase + r, bt1 = rBase + r + 8;
                float g0 = g_cg[(size_t)bt0 * 4 + h] * CSCALE;
                float g1 = g_cg[(size_t)bt1 * 4 + h] * CSCALE;
                unsigned hh, ll;
                split2bf((A[0] + b0) * g0, (A[1] + b1) * g0, hh, ll);
                __nv_bfloat16* op = g_QgS + (size_t)bt0 * KPHYS + cc;
                *(unsigned*)(op) = hh; *(unsigned*)(op + 512) = ll;
                split2bf((A[2] + b0) * g1, (A[3] + b1) * g1, hh, ll);
                op = g_QgS + (size_t)bt1 * KPHYS + cc;
                *(unsigned*)(op) = hh; *(unsigned*)(op + 512) = ll;
            }
    }
}

// ===================== logits GEMM + fused argmax partials ==================
__global__ __launch_bounds__(256, 2)
void gemm_logits_mma(float* __restrict__ out) {
    extern __shared__ __align__(1024) char smem[];
    const int tid  = threadIdx.x;
    const int wid  = tid >> 5, lane = tid & 31;
    const int wm   = wid & 1;
    const int wn   = wid >> 1;
    const int b     = blockIdx.z;
    const int nBase = blockIdx.y * 128;
    const int tBase = blockIdx.x * 128;
    const uint32_t sb = smem_to_u32(smem);

    float acc[16][4] = {};
    gemm1536_core((const char*)(g_KpS + (size_t)nBase * KPHYS),
                  (const char*)(g_QgS + ((size_t)b * TDIM + tBase) * KPHYS),
                  sb, tid, acc);

    __syncthreads();   // smem free; safe to alias for argmax below

    // ---- write logits ----
    float* obase = out + (size_t)b * NCB * TDIM + (size_t)nBase * TDIM + tBase;
    #pragma unroll
    for (int mi = 0; mi < 4; mi++) {
        #pragma unroll
        for (int nj = 0; nj < 4; nj++) {
            float* A = acc[mi * 4 + nj];
            int r  = wm * 64 + mi * 16 + (lane >> 2);
            int cc = wn * 32 + nj * 8 + 2 * (lane & 3);
            *(float2*)(obase + (size_t)r * TDIM + cc)       = make_float2(A[0], A[1]);
            *(float2*)(obase + (size_t)(r + 8) * TDIM + cc) = make_float2(A[2], A[3]);
        }
    }

    // ---- fused argmax partial over this CTA's 128 rows ----
    float mv[8]; int mi_[8];
    #pragma unroll
    for (int nj = 0; nj < 4; nj++) {
        #pragma unroll
        for (int cc = 0; cc < 2; cc++) {
            int key = nj * 2 + cc;
            float best = -INFINITY; int bidx = 0;
            #pragma unroll
            for (int mi = 0; mi < 4; mi++) {
                #pragma unroll
                for (int hf = 0; hf < 2; hf++) {
                    float v = acc[mi * 4 + nj][hf * 2 + cc];
                    int   ix = nBase + wm * 64 + mi * 16 + (lane >> 2) + hf * 8;
                    if (v > best || (v == best && ix < bidx)) { best = v; bidx = ix; }
                }
            }
            mv[key] = best; mi_[key] = bidx;
        }
    }
    #pragma unroll
    for (int off = 4; off < 32; off <<= 1) {
        #pragma unroll
        for (int key = 0; key < 8; key++) {
            float ov = __shfl_xor_sync(0xffffffff, mv[key], off);
            int   oi = __shfl_xor_sync(0xffffffff, mi_[key], off);
            if (ov > mv[key] || (ov == mv[key] && oi < mi_[key])) {
                mv[key] = ov; mi_[key] = oi;
            }
        }
    }
    float* sval = (float*)smem;               // [2][128]
    int*   sidx = (int*)(smem + 2 * 128 * 4); // [2][128]
    if (lane < 4) {
        #pragma unroll
        for (int nj = 0; nj < 4; nj++)
            #pragma unroll
            for (int cc = 0; cc < 2; cc++) {
                int col = wn * 32 + nj * 8 + 2 * lane + cc;
                sval[wm * 128 + col] = mv[nj * 2 + cc];
                sidx[wm * 128 + col] = mi_[nj * 2 + cc];
            }
    }
    __syncthreads();
    if (tid < 128) {
        float v0 = sval[tid],      v1 = sval[128 + tid];
        int   i0 = sidx[tid],      i1 = sidx[128 + tid];
        bool take1 = (v1 > v0) || (v1 == v0 && i1 < i0);
        size_t o = ((size_t)blockIdx.y * BATCH + b) * TDIM + tBase + tid;
        g_pmax[o] = take1 ? v1 : v0;
        g_pidx[o] = take1 ? i1 : i0;
    }
}

// ------ fused final argmax (32 slices) + smem-staged z_q gather -------------
// Phase A: 32 threads finish argmax. Phase B: warps fetch the 32 selected V
// rows coalesced into padded smem. Phase C: coalesced writes to zq.
#define ZQ_PITCH 517
#define ZQ_SMEM  (32 * ZQ_PITCH * 4)     // 66176 B

__global__ void argmax_zq_kernel(float* __restrict__ idx_out, float* __restrict__ zq) {
    extern __shared__ float sV[];            // [32][ZQ_PITCH]
    __shared__ int sIdx[32];
    int b = blockIdx.y;
    int t0 = blockIdx.x * 32;
    int lane = threadIdx.x & 31;
    int wid  = threadIdx.x >> 5;

    if (threadIdx.x < 32) {
        int t = t0 + threadIdx.x;
        float best = -INFINITY; int bi = 0x7fffffff;
        #pragma unroll
        for (int z = 0; z < NBLOCKS; z++) {
            float x = g_pmax[((size_t)z * BATCH + b) * TDIM + t];
            int  ii = g_pidx[((size_t)z * BATCH + b) * TDIM + t];
            if (x > best || (x == best && ii < bi)) { best = x; bi = ii; }
        }
        g_idx[b * TDIM + t] = bi;
        sIdx[threadIdx.x] = bi;
        idx_out[b * TDIM + t] = (float)bi;
    }
    __syncthreads();

    // Phase B: each warp stages 4 rows (t-local = wid, wid+8, wid+16, wid+24)
    #pragma unroll
    for (int r4 = 0; r4 < 4; r4++) {
        int tl = wid + r4 * 8;
        const float* v = g_V + (size_t)sIdx[tl] * CDIM;
        #pragma unroll
        for (int k = 0; k < CDIM / 32; k++)
            sV[tl * ZQ_PITCH + k * 32 + lane] = __ldg(&v[k * 32 + lane]);
    }
    __syncthreads();

    // Phase C: cgrp covers 64 c's; lanes give consecutive t -> 128B stores.
    int cgrp = wid;
    float* o = zq + (size_t)b * CDIM * TDIM + t0 + lane;
    int c0 = cgrp * 64;
    #pragma unroll 8
    for (int c = c0; c < c0 + 64; c++)
        o[(size_t)c * TDIM] = sV[lane * ZQ_PITCH + c];
}

// ---------------- launcher --------------------------------------------------
extern "C" void kernel_launch(void* const* d_in, const int* in_sizes, int n_in,
                              void* d_out, int out_size) {
    const float* hidden = (const float*)d_in[0];  // [B,C,T]
    const float* cb     = (const float*)d_in[1];  // [N,C]
    const float* Wq = (const float*)d_in[2]; const float* bq = (const float*)d_in[3];
    const float* Wk = (const float*)d_in[4]; const float* bk = (const float*)d_in[5];
    const float* Wv = (const float*)d_in[6]; const float* bv = (const float*)d_in[7];
    const float* Wp = (const float*)d_in[8]; const float* bp = (const float*)d_in[9];

    float* out        = (float*)d_out;
    float* out_logits = out;                                       // B*N*T
    float* out_idx    = out + (size_t)BATCH * NCB * TDIM;          // B*T
    float* out_zq     = out_idx + (size_t)BATCH * TDIM;            // B*C*T

    cudaFuncSetAttribute(gemm_proj_all,
                         cudaFuncAttributeMaxDynamicSharedMemorySize, GEMM_SMEM);
    cudaFuncSetAttribute(gemm_logits_mma,
                         cudaFuncAttributeMaxDynamicSharedMemorySize, GEMM_SMEM);
    cudaFuncSetAttribute(argmax_zq_kernel,
                         cudaFuncAttributeMaxDynamicSharedMemorySize, ZQ_SMEM);

    // all prep (cb split, W splits, hidden split + cg)
    prep_all_kernel<<<3072, 256>>>(cb, Wq, Wk, Wv, hidden, Wp, bp);
    // all projections in one launch (tile 128x128)
    gemm_proj_all<<<dim3(4, 128), 256, GEMM_SMEM>>>(bq, bk, bv);
    // logits + fused argmax partials
    gemm_logits_mma<<<dim3(TDIM / 128, NCB / 128, BATCH), 256, GEMM_SMEM>>>(out_logits);
    // fused final argmax + smem-staged z_q gather
    argmax_zq_kernel<<<dim3(TDIM / 32, BATCH), 256, ZQ_SMEM>>>(out_idx, out_zq);
}

// round 14
// speedup vs baseline: 1.5274x; 1.5274x over previous
#include <cuda_runtime.h>
#include <cuda_bf16.h>
#include <math.h>
#include <stdint.h>

// Problem constants
#define BATCH 4
#define CDIM  512
#define TDIM  2048
#define NCB   4096
#define HH    4
// Physical split storage: [hi|lo] = 1024 bf16 = 2048 B per row.
// Logical K = 1536: products Ah*Bh + Al*Bh + Ah*Bl per 64-col ci-group.
#define KPHYS 1024
#define ROWB  2048
#define CSCALE 0.04419417382415922f   // 1/(sqrt(128)*sqrt(4))

#define NBLOCKS (NCB / 128)        // 32 partial-argmax slices

// ---------------- scratch (device globals; no runtime allocation) -----------
__device__ __nv_bfloat16 g_AcbS[(size_t)NCB * KPHYS];          // cb split [hi|lo]
__device__ __nv_bfloat16 g_HsS [(size_t)BATCH * TDIM * KPHYS]; // hs^T split [hi|lo]
__device__ __nv_bfloat16 g_WTS [3][(size_t)CDIM * KPHYS];      // Wq,Wk,Wv^T [hi|lo]
__device__ __nv_bfloat16 g_KpS[(size_t)NCB * KPHYS];           // K' split [hi|lo]
__device__ __nv_bfloat16 g_QgS[(size_t)BATCH * TDIM * KPHYS];  // Qg split [hi|lo]
__device__ float g_V [(size_t)NCB * CDIM];
__device__ float g_cg[(size_t)BATCH * TDIM * HH];   // includes bias
__device__ int   g_idx[(size_t)BATCH * TDIM];
__device__ float g_pmax[NBLOCKS * BATCH * TDIM];
__device__ int   g_pidx[NBLOCKS * BATCH * TDIM];

// ======================= helpers ============================================
#define SMEM_SWIZZLE_128B(off) ((off) ^ (((off) >> 3) & 0x70))
#define CP_ASYNC16(dst, src) \
    asm volatile("cp.async.cg.shared.global [%0], [%1], 16;" :: "r"(dst), "l"(src))
#define CP_ASYNC_COMMIT() asm volatile("cp.async.commit_group;" ::: "memory")

__device__ __forceinline__ uint32_t smem_to_u32(const void* p) {
    uint32_t a;
    asm("{ .reg .u64 t; cvta.to.shared.u64 t, %1; cvt.u32.u64 %0, t; }"
        : "=r"(a) : "l"(p));
    return a;
}
__device__ __forceinline__ void ldsm_x4(uint32_t& r0, uint32_t& r1, uint32_t& r2,
                                        uint32_t& r3, uint32_t addr) {
    asm volatile("ldmatrix.sync.aligned.m8n8.x4.shared.b16 {%0,%1,%2,%3}, [%4];"
                 : "=r"(r0), "=r"(r1), "=r"(r2), "=r"(r3) : "r"(addr));
}
__device__ __forceinline__ void mma16816(float* c, uint32_t a0, uint32_t a1,
                                         uint32_t a2, uint32_t a3,
                                         uint32_t b0, uint32_t b1) {
    asm volatile(
        "mma.sync.aligned.m16n8k16.row.col.f32.bf16.bf16.f32 "
        "{%0,%1,%2,%3}, {%4,%5,%6,%7}, {%8,%9}, {%0,%1,%2,%3};"
        : "+f"(c[0]), "+f"(c[1]), "+f"(c[2]), "+f"(c[3])
        : "r"(a0), "r"(a1), "r"(a2), "r"(a3), "r"(b0), "r"(b1));
}
__device__ __forceinline__ void split2bf(float v0, float v1, unsigned& hu, unsigned& lu) {
    __nv_bfloat16 h0 = __float2bfloat16(v0), h1 = __float2bfloat16(v1);
    float r0 = v0 - __bfloat162float(h0), r1 = v1 - __bfloat162float(h1);
    __nv_bfloat16 l0 = __float2bfloat16(r0), l1 = __float2bfloat16(r1);
    __nv_bfloat162 ph = __halves2bfloat162(h0, h1);
    __nv_bfloat162 pl = __halves2bfloat162(l0, l1);
    hu = *reinterpret_cast<unsigned*>(&ph);
    lu = *reinterpret_cast<unsigned*>(&pl);
}
__device__ __forceinline__ void split1bf(float v, __nv_bfloat16& h, __nv_bfloat16& l) {
    h = __float2bfloat16(v);
    l = __float2bfloat16(v - __bfloat162float(h));
}

// ====== canonical logical-K=1536 bf16 mma core with tile reuse ==============
// (R9 core: 16 loads, 24 MMA chunks, 2 syncs/group)
#define GEMM_STAGE  32768                    // A 16KB + B 16KB
#define GEMM_SMEM   (3 * GEMM_STAGE)         // 98304

__device__ __forceinline__ void gemm1536_core(const char* Abase, const char* Bbase,
                                              uint32_t sb, int tid,
                                              float (&acc)[16][4]) {
    const int lane = tid & 31;
    const int wid  = tid >> 5;
    const int wm = wid & 1, wn = wid >> 1;

    #define GLOAD(j) do { \
        uint32_t _as = sb + ((j) % 3) * GEMM_STAGE; \
        uint32_t _bs = _as + 16384; \
        size_t _ko = (size_t)(((j) & 1) ? 8 + ((j) >> 1) : ((j) >> 1)) * 128; \
        _Pragma("unroll") \
        for (int _i = 0; _i < 4; _i++) { \
            int _u = tid + _i * 256; \
            int _r = _u >> 3, _c16 = (_u & 7) * 16; \
            CP_ASYNC16(_as + SMEM_SWIZZLE_128B(_r * 128 + _c16), \
                       Abase + (size_t)_r * ROWB + _ko + _c16); \
        } \
        _Pragma("unroll") \
        for (int _i = 0; _i < 4; _i++) { \
            int _u = tid + _i * 256; \
            int _r = _u >> 3, _c16 = (_u & 7) * 16; \
            CP_ASYNC16(_bs + SMEM_SWIZZLE_128B(_r * 128 + _c16), \
                       Bbase + (size_t)_r * ROWB + _ko + _c16); \
        } \
        CP_ASYNC_COMMIT(); \
    } while (0)

    #define MMA_CHUNK(Astage, Bstage) do { \
        uint32_t _As = sb + (Astage) * GEMM_STAGE; \
        uint32_t _Bs = sb + (Bstage) * GEMM_STAGE + 16384; \
        _Pragma("unroll") \
        for (int kk = 0; kk < 4; kk++) { \
            uint32_t a[4][4]; \
            _Pragma("unroll") \
            for (int mi = 0; mi < 4; mi++) { \
                int row = wm * 64 + mi * 16 + (lane & 15); \
                int u   = kk * 2 + (lane >> 4); \
                ldsm_x4(a[mi][0], a[mi][1], a[mi][2], a[mi][3], \
                        _As + row * 128 + ((u ^ (row & 7)) << 4)); \
            } \
            uint32_t bf[2][4]; \
            _Pragma("unroll") \
            for (int nf = 0; nf < 2; nf++) { \
                int row = wn * 32 + nf * 16 + ((lane >> 4) << 3) + (lane & 7); \
                int u   = kk * 2 + ((lane >> 3) & 1); \
                ldsm_x4(bf[nf][0], bf[nf][1], bf[nf][2], bf[nf][3], \
                        _Bs + row * 128 + ((u ^ (row & 7)) << 4)); \
            } \
            _Pragma("unroll") \
            for (int mi = 0; mi < 4; mi++) \
                _Pragma("unroll") \
                for (int nj = 0; nj < 4; nj++) \
                    mma16816(acc[mi * 4 + nj], \
                             a[mi][0], a[mi][1], a[mi][2], a[mi][3], \
                             bf[nj >> 1][(nj & 1) * 2], bf[nj >> 1][(nj & 1) * 2 + 1]); \
        } \
    } while (0)

    GLOAD(0); GLOAD(1); GLOAD(2);

    #pragma unroll
    for (int g = 0; g < 8; g++) {
        const int sA = (2 * g) % 3;
        const int sB = (2 * g + 1) % 3;

        if (g == 0) asm volatile("cp.async.wait_group 2;" ::: "memory");
        else        asm volatile("cp.async.wait_group 0;" ::: "memory");
        __syncthreads();
        if (g >= 1) {
            GLOAD(2 * g + 1);
            if (2 * g + 2 <= 15) GLOAD(2 * g + 2);
        }
        MMA_CHUNK(sA, sA);

        if (g == 7) asm volatile("cp.async.wait_group 0;" ::: "memory");
        else        asm volatile("cp.async.wait_group 1;" ::: "memory");
        __syncthreads();
        MMA_CHUNK(sB, sA);

        MMA_CHUNK(sA, sB);
    }
    #undef GLOAD
    #undef MMA_CHUNK
}

// ===================== merged prep kernel ===================================
// bx < 2048            : cb split
// 2048 <= bx < 2816    : Wq/Wk/Wv transpose-split
// 2816 <= bx < 3072    : hidden transpose-split + fused head gates
__global__ void prep_all_kernel(const float* __restrict__ cb,
                                const float* __restrict__ Wq,
                                const float* __restrict__ Wk,
                                const float* __restrict__ Wv,
                                const float* __restrict__ hidden,
                                const float* __restrict__ Wp,
                                const float* __restrict__ bp) {
    __shared__ float tile[32][33];
    __shared__ float sWp[CDIM * HH];
    int bx = blockIdx.x;
    if (bx < 2048) {
        int idx = bx * 256 + threadIdx.x;
        int n  = idx >> 7;
        int c4 = (idx & 127) * 4;
        float4 v = *(const float4*)(cb + (size_t)n * CDIM + c4);
        unsigned h0, l0, h1, l1;
        split2bf(v.x, v.y, h0, l0);
        split2bf(v.z, v.w, h1, l1);
        __nv_bfloat16* op = g_AcbS + (size_t)n * KPHYS + c4;
        *(uint2*)(op)       = make_uint2(h0, h1);
        *(uint2*)(op + 512) = make_uint2(l0, l1);
    } else if (bx < 2816) {
        int bid = bx - 2048;          // 0..767
        int z   = bid >> 8;           // 0..2
        int rem = bid & 255;
        int ci0 = (rem >> 4) * 32, c0 = (rem & 15) * 32;
        const float* W = (z == 0) ? Wq : (z == 1) ? Wk : Wv;
        int tx = threadIdx.x & 31, ty = threadIdx.x >> 5;
        #pragma unroll
        for (int k = 0; k < 4; k++)
            tile[ty + 8 * k][tx] = W[(size_t)(ci0 + ty + 8 * k) * CDIM + c0 + tx];
        __syncthreads();
        __nv_bfloat16* base = g_WTS[z];
        #pragma unroll
        for (int k = 0; k < 4; k++) {
            int c = c0 + ty + 8 * k;
            float v = tile[tx][ty + 8 * k];
            __nv_bfloat16 h, l; split1bf(v, h, l);
            __nv_bfloat16* op = base + (size_t)c * KPHYS + ci0 + tx;
            op[0] = h; op[512] = l;
        }
    } else {
        int r  = bx - 2816;           // 0..255
        int b  = r >> 6;
        int t0 = (r & 63) * 32;
        int tx = threadIdx.x & 31, ty = threadIdx.x >> 5;
        const float* hp = hidden + (size_t)b * CDIM * TDIM;

        #pragma unroll
        for (int i = 0; i < 8; i++)
            sWp[threadIdx.x + i * 256] = Wp[threadIdx.x + i * 256];

        float cgacc = 0.f;
        int tl = threadIdx.x >> 2, hh = threadIdx.x & 3;

        for (int ci0 = 0; ci0 < CDIM; ci0 += 32) {
            __syncthreads();
            #pragma unroll
            for (int k = 0; k < 4; k++)
                tile[ty + 8 * k][tx] = hp[(size_t)(ci0 + ty + 8 * k) * TDIM + t0 + tx];
            __syncthreads();
            #pragma unroll
            for (int k = 0; k < 4; k++) {
                int t = t0 + ty + 8 * k;
                float v = tile[tx][ty + 8 * k];
                __nv_bfloat16 h, l; split1bf(v, h, l);
                __nv_bfloat16* op = g_HsS + ((size_t)b * TDIM + t) * KPHYS + ci0 + tx;
                op[0] = h; op[512] = l;
            }
            if (threadIdx.x < 128) {
                #pragma unroll 8
                for (int ci = 0; ci < 32; ci++)
                    cgacc += tile[ci][tl] * sWp[(ci0 + ci) * 4 + hh];
            }
        }
        if (threadIdx.x < 128) {
            int bt = b * TDIM + t0 + tl;
            g_cg[(size_t)bt * 4 + hh] = cgacc + bp[hh];
        }
    }
}

// ===================== merged projection GEMMs (tensor) =====================
__global__ __launch_bounds__(256, 2)
void gemm_proj_all(const float* __restrict__ bq, const float* __restrict__ bk,
                   const float* __restrict__ bv) {
    extern __shared__ __align__(1024) char smem[];
    const int tid = threadIdx.x;
    const int lane = tid & 31, wid = tid >> 5;
    const int wm = wid & 1, wn = wid >> 1;
    const int y = blockIdx.y;
    const int cBase = blockIdx.x * 128;
    const uint32_t sb = smem_to_u32(smem);

    const char* Abase;
    const char* Bbase;
    int rBase;
    int mode;           // 0=K', 1=V, 2=Qg
    if (y < 32)       { mode = 0; rBase = y * 128;
                        Abase = (const char*)(g_AcbS + (size_t)rBase * KPHYS);
                        Bbase = (const char*)(g_WTS[1] + (size_t)cBase * KPHYS); }
    else if (y < 64)  { mode = 1; rBase = (y - 32) * 128;
                        Abase = (const char*)(g_AcbS + (size_t)rBase * KPHYS);
                        Bbase = (const char*)(g_WTS[2] + (size_t)cBase * KPHYS); }
    else              { mode = 2; rBase = (y - 64) * 128;
                        Abase = (const char*)(g_HsS + (size_t)rBase * KPHYS);
                        Bbase = (const char*)(g_WTS[0] + (size_t)cBase * KPHYS); }

    float acc[16][4] = {};
    gemm1536_core(Abase, Bbase, sb, tid, acc);

    if (mode == 0) {
        #pragma unroll
        for (int mi = 0; mi < 4; mi++)
            #pragma unroll
            for (int nj = 0; nj < 4; nj++) {
                float* A = acc[mi * 4 + nj];
                int r  = wm * 64 + mi * 16 + (lane >> 2);
                int cc = cBase + wn * 32 + nj * 8 + 2 * (lane & 3);
                float b0 = bk[cc], b1 = bk[cc + 1];
                unsigned h, l;
                split2bf(A[0] + b0, A[1] + b1, h, l);
                __nv_bfloat16* op = g_KpS + (size_t)(rBase + r) * KPHYS + cc;
                *(unsigned*)(op) = h; *(unsigned*)(op + 512) = l;
                split2bf(A[2] + b0, A[3] + b1, h, l);
                op = g_KpS + (size_t)(rBase + r + 8) * KPHYS + cc;
                *(unsigned*)(op) = h; *(unsigned*)(op + 512) = l;
            }
    } else if (mode == 1) {
        #pragma unroll
        for (int mi = 0; mi < 4; mi++)
            #pragma unroll
            for (int nj = 0; nj < 4; nj++) {
                float* A = acc[mi * 4 + nj];
                int r  = wm * 64 + mi * 16 + (lane >> 2);
                int cc = cBase + wn * 32 + nj * 8 + 2 * (lane & 3);
                float b0 = bv[cc], b1 = bv[cc + 1];
                *(float2*)(g_V + (size_t)(rBase + r) * CDIM + cc) =
                    make_float2(A[0] + b0, A[1] + b1);
                *(float2*)(g_V + (size_t)(rBase + r + 8) * CDIM + cc) =
                    make_float2(A[2] + b0, A[3] + b1);
            }
    } else {
        const int h = blockIdx.x;
        #pragma unroll
        for (int mi = 0; mi < 4; mi++)
            #pragma unroll
            for (int nj = 0; nj < 4; nj++) {
                float* A = acc[mi * 4 + nj];
                int r  = wm * 64 + mi * 16 + (lane >> 2);
                int cc = cBase + wn * 32 + nj * 8 + 2 * (lane & 3);
                float b0 = bq[cc], b1 = bq[cc + 1];
                int bt0 = rBase + r, bt1 = rBase + r + 8;
                float g0 = g_cg[(size_t)bt0 * 4 + h] * CSCALE;
                float g1 = g_cg[(size_t)bt1 * 4 + h] * CSCALE;
                unsigned hh, ll;
                split2bf((A[0] + b0) * g0, (A[1] + b1) * g0, hh, ll);
                __nv_bfloat16* op = g_QgS + (size_t)bt0 * KPHYS + cc;
                *(unsigned*)(op) = hh; *(unsigned*)(op + 512) = ll;
                split2bf((A[2] + b0) * g1, (A[3] + b1) * g1, hh, ll);
                op = g_QgS + (size_t)bt1 * KPHYS + cc;
                *(unsigned*)(op) = hh; *(unsigned*)(op + 512) = ll;
            }
    }
}

// ===================== logits GEMM + fused argmax partials ==================
__global__ __launch_bounds__(256, 2)
void gemm_logits_mma(float* __restrict__ out) {
    extern __shared__ __align__(1024) char smem[];
    const int tid  = threadIdx.x;
    const int wid  = tid >> 5, lane = tid & 31;
    const int wm   = wid & 1;
    const int wn   = wid >> 1;
    const int b     = blockIdx.z;
    const int nBase = blockIdx.y * 128;
    const int tBase = blockIdx.x * 128;
    const uint32_t sb = smem_to_u32(smem);

    float acc[16][4] = {};
    gemm1536_core((const char*)(g_KpS + (size_t)nBase * KPHYS),
                  (const char*)(g_QgS + ((size_t)b * TDIM + tBase) * KPHYS),
                  sb, tid, acc);

    __syncthreads();   // smem free; safe to alias for argmax below

    // ---- write logits ----
    float* obase = out + (size_t)b * NCB * TDIM + (size_t)nBase * TDIM + tBase;
    #pragma unroll
    for (int mi = 0; mi < 4; mi++) {
        #pragma unroll
        for (int nj = 0; nj < 4; nj++) {
            float* A = acc[mi * 4 + nj];
            int r  = wm * 64 + mi * 16 + (lane >> 2);
            int cc = wn * 32 + nj * 8 + 2 * (lane & 3);
            *(float2*)(obase + (size_t)r * TDIM + cc)       = make_float2(A[0], A[1]);
            *(float2*)(obase + (size_t)(r + 8) * TDIM + cc) = make_float2(A[2], A[3]);
        }
    }

    // ---- fused argmax partial over this CTA's 128 rows ----
    float mv[8]; int mi_[8];
    #pragma unroll
    for (int nj = 0; nj < 4; nj++) {
        #pragma unroll
        for (int cc = 0; cc < 2; cc++) {
            int key = nj * 2 + cc;
            float best = -INFINITY; int bidx = 0;
            #pragma unroll
            for (int mi = 0; mi < 4; mi++) {
                #pragma unroll
                for (int hf = 0; hf < 2; hf++) {
                    float v = acc[mi * 4 + nj][hf * 2 + cc];
                    int   ix = nBase + wm * 64 + mi * 16 + (lane >> 2) + hf * 8;
                    if (v > best || (v == best && ix < bidx)) { best = v; bidx = ix; }
                }
            }
            mv[key] = best; mi_[key] = bidx;
        }
    }
    #pragma unroll
    for (int off = 4; off < 32; off <<= 1) {
        #pragma unroll
        for (int key = 0; key < 8; key++) {
            float ov = __shfl_xor_sync(0xffffffff, mv[key], off);
            int   oi = __shfl_xor_sync(0xffffffff, mi_[key], off);
            if (ov > mv[key] || (ov == mv[key] && oi < mi_[key])) {
                mv[key] = ov; mi_[key] = oi;
            }
        }
    }
    float* sval = (float*)smem;               // [2][128]
    int*   sidx = (int*)(smem + 2 * 128 * 4); // [2][128]
    if (lane < 4) {
        #pragma unroll
        for (int nj = 0; nj < 4; nj++)
            #pragma unroll
            for (int cc = 0; cc < 2; cc++) {
                int col = wn * 32 + nj * 8 + 2 * lane + cc;
                sval[wm * 128 + col] = mv[nj * 2 + cc];
                sidx[wm * 128 + col] = mi_[nj * 2 + cc];
            }
    }
    __syncthreads();
    if (tid < 128) {
        float v0 = sval[tid],      v1 = sval[128 + tid];
        int   i0 = sidx[tid],      i1 = sidx[128 + tid];
        bool take1 = (v1 > v0) || (v1 == v0 && i1 < i0);
        size_t o = ((size_t)blockIdx.y * BATCH + b) * TDIM + tBase + tid;
        g_pmax[o] = take1 ? v1 : v0;
        g_pidx[o] = take1 ? i1 : i0;
    }
}

// ------ fused final argmax (32 slices) + smem-staged z_q gather -------------
// Phase A: 32 threads finish argmax. Phase B: warps fetch the 32 selected V
// rows coalesced into padded smem. Phase C: coalesced writes to zq.
#define ZQ_PITCH 517
#define ZQ_SMEM  (32 * ZQ_PITCH * 4)     // 66176 B

__global__ void argmax_zq_kernel(float* __restrict__ idx_out, float* __restrict__ zq) {
    extern __shared__ float sV[];            // [32][ZQ_PITCH]
    __shared__ int sIdx[32];
    int b = blockIdx.y;
    int t0 = blockIdx.x * 32;
    int lane = threadIdx.x & 31;
    int wid  = threadIdx.x >> 5;

    if (threadIdx.x < 32) {
        int t = t0 + threadIdx.x;
        float best = -INFINITY; int bi = 0x7fffffff;
        #pragma unroll
        for (int z = 0; z < NBLOCKS; z++) {
            float x = g_pmax[((size_t)z * BATCH + b) * TDIM + t];
            int  ii = g_pidx[((size_t)z * BATCH + b) * TDIM + t];
            if (x > best || (x == best && ii < bi)) { best = x; bi = ii; }
        }
        g_idx[b * TDIM + t] = bi;
        sIdx[threadIdx.x] = bi;
        idx_out[b * TDIM + t] = (float)bi;
    }
    __syncthreads();

    // Phase B: each warp stages 4 rows (t-local = wid, wid+8, wid+16, wid+24)
    #pragma unroll
    for (int r4 = 0; r4 < 4; r4++) {
        int tl = wid + r4 * 8;
        const float* v = g_V + (size_t)sIdx[tl] * CDIM;
        #pragma unroll
        for (int k = 0; k < CDIM / 32; k++)
            sV[tl * ZQ_PITCH + k * 32 + lane] = __ldg(&v[k * 32 + lane]);
    }
    __syncthreads();

    // Phase C: cgrp covers 64 c's; lanes give consecutive t -> 128B stores.
    int cgrp = wid;
    float* o = zq + (size_t)b * CDIM * TDIM + t0 + lane;
    int c0 = cgrp * 64;
    #pragma unroll 8
    for (int c = c0; c < c0 + 64; c++)
        o[(size_t)c * TDIM] = sV[lane * ZQ_PITCH + c];
}

// ---------------- launcher --------------------------------------------------
extern "C" void kernel_launch(void* const* d_in, const int* in_sizes, int n_in,
                              void* d_out, int out_size) {
    const float* hidden = (const float*)d_in[0];  // [B,C,T]
    const float* cb     = (const float*)d_in[1];  // [N,C]
    const float* Wq = (const float*)d_in[2]; const float* bq = (const float*)d_in[3];
    const float* Wk = (const float*)d_in[4]; const float* bk = (const float*)d_in[5];
    const float* Wv = (const float*)d_in[6]; const float* bv = (const float*)d_in[7];
    const float* Wp = (const float*)d_in[8]; const float* bp = (const float*)d_in[9];

    float* out        = (float*)d_out;
    float* out_logits = out;                                       // B*N*T
    float* out_idx    = out + (size_t)BATCH * NCB * TDIM;          // B*T
    float* out_zq     = out_idx + (size_t)BATCH * TDIM;            // B*C*T

    cudaFuncSetAttribute(gemm_proj_all,
                         cudaFuncAttributeMaxDynamicSharedMemorySize, GEMM_SMEM);
    cudaFuncSetAttribute(gemm_logits_mma,
                         cudaFuncAttributeMaxDynamicSharedMemorySize, GEMM_SMEM);
    cudaFuncSetAttribute(argmax_zq_kernel,
                         cudaFuncAttributeMaxDynamicSharedMemorySize, ZQ_SMEM);

    // all prep (cb split, W splits, hidden split + cg)
    prep_all_kernel<<<3072, 256>>>(cb, Wq, Wk, Wv, hidden, Wp, bp);
    // all projections in one launch (tile 128x128)
    gemm_proj_all<<<dim3(4, 128), 256, GEMM_SMEM>>>(bq, bk, bv);
    // logits + fused argmax partials
    gemm_logits_mma<<<dim3(TDIM / 128, NCB / 128, BATCH), 256, GEMM_SMEM>>>(out_logits);
    // fused final argmax + smem-staged z_q gather
    argmax_zq_kernel<<<dim3(TDIM / 32, BATCH), 256, ZQ_SMEM>>>(out_idx, out_zq);
}

// round 16
// speedup vs baseline: 1.5279x; 1.0003x over previous
#include <cuda_runtime.h>
#include <cuda_bf16.h>
#include <math.h>
#include <stdint.h>

// Problem constants
#define BATCH 4
#define CDIM  512
#define TDIM  2048
#define NCB   4096
#define HH    4
// Physical split storage: [hi|lo] = 1024 bf16 = 2048 B per row.
// Logical K = 1536: products Ah*Bh + Al*Bh + Ah*Bl per 64-col ci-group.
#define KPHYS 1024
#define ROWB  2048
#define CSCALE 0.04419417382415922f   // 1/(sqrt(128)*sqrt(4))

#define NBLOCKS (NCB / 128)        // 32 partial-argmax slices

// ---------------- scratch (device globals; no runtime allocation) -----------
__device__ __nv_bfloat16 g_AcbS[(size_t)NCB * KPHYS];          // cb split [hi|lo]
__device__ __nv_bfloat16 g_HsS [(size_t)BATCH * TDIM * KPHYS]; // hs^T split [hi|lo]
__device__ __nv_bfloat16 g_WTS [3][(size_t)CDIM * KPHYS];      // Wq,Wk,Wv^T [hi|lo]
__device__ __nv_bfloat16 g_KpS[(size_t)NCB * KPHYS];           // K' split [hi|lo]
__device__ __nv_bfloat16 g_QgS[(size_t)BATCH * TDIM * KPHYS];  // Qg split [hi|lo]
__device__ float g_V [(size_t)NCB * CDIM];
__device__ float g_cg[(size_t)BATCH * TDIM * HH];   // includes bias
__device__ int   g_idx[(size_t)BATCH * TDIM];
__device__ float g_pmax[NBLOCKS * BATCH * TDIM];
__device__ int   g_pidx[NBLOCKS * BATCH * TDIM];

// ======================= helpers ============================================
#define SMEM_SWIZZLE_128B(off) ((off) ^ (((off) >> 3) & 0x70))
#define CP_ASYNC16(dst, src) \
    asm volatile("cp.async.cg.shared.global [%0], [%1], 16;" :: "r"(dst), "l"(src))
#define CP_ASYNC_COMMIT() asm volatile("cp.async.commit_group;" ::: "memory")

__device__ __forceinline__ uint32_t smem_to_u32(const void* p) {
    uint32_t a;
    asm("{ .reg .u64 t; cvta.to.shared.u64 t, %1; cvt.u32.u64 %0, t; }"
        : "=r"(a) : "l"(p));
    return a;
}
__device__ __forceinline__ void ldsm_x4(uint32_t& r0, uint32_t& r1, uint32_t& r2,
                                        uint32_t& r3, uint32_t addr) {
    asm volatile("ldmatrix.sync.aligned.m8n8.x4.shared.b16 {%0,%1,%2,%3}, [%4];"
                 : "=r"(r0), "=r"(r1), "=r"(r2), "=r"(r3) : "r"(addr));
}
__device__ __forceinline__ void mma16816(float* c, uint32_t a0, uint32_t a1,
                                         uint32_t a2, uint32_t a3,
                                         uint32_t b0, uint32_t b1) {
    asm volatile(
        "mma.sync.aligned.m16n8k16.row.col.f32.bf16.bf16.f32 "
        "{%0,%1,%2,%3}, {%4,%5,%6,%7}, {%8,%9}, {%0,%1,%2,%3};"
        : "+f"(c[0]), "+f"(c[1]), "+f"(c[2]), "+f"(c[3])
        : "r"(a0), "r"(a1), "r"(a2), "r"(a3), "r"(b0), "r"(b1));
}
__device__ __forceinline__ void split2bf(float v0, float v1, unsigned& hu, unsigned& lu) {
    __nv_bfloat16 h0 = __float2bfloat16(v0), h1 = __float2bfloat16(v1);
    float r0 = v0 - __bfloat162float(h0), r1 = v1 - __bfloat162float(h1);
    __nv_bfloat16 l0 = __float2bfloat16(r0), l1 = __float2bfloat16(r1);
    __nv_bfloat162 ph = __halves2bfloat162(h0, h1);
    __nv_bfloat162 pl = __halves2bfloat162(l0, l1);
    hu = *reinterpret_cast<unsigned*>(&ph);
    lu = *reinterpret_cast<unsigned*>(&pl);
}

// ====== canonical logical-K=1536 bf16 mma core with tile reuse ==============
// (R9 core: 16 loads, 24 MMA chunks, 2 syncs/group)
#define GEMM_STAGE  32768                    // A 16KB + B 16KB
#define GEMM_SMEM   (3 * GEMM_STAGE)         // 98304

__device__ __forceinline__ void gemm1536_core(const char* Abase, const char* Bbase,
                                              uint32_t sb, int tid,
                                              float (&acc)[16][4]) {
    const int lane = tid & 31;
    const int wid  = tid >> 5;
    const int wm = wid & 1, wn = wid >> 1;

    #define GLOAD(j) do { \
        uint32_t _as = sb + ((j) % 3) * GEMM_STAGE; \
        uint32_t _bs = _as + 16384; \
        size_t _ko = (size_t)(((j) & 1) ? 8 + ((j) >> 1) : ((j) >> 1)) * 128; \
        _Pragma("unroll") \
        for (int _i = 0; _i < 4; _i++) { \
            int _u = tid + _i * 256; \
            int _r = _u >> 3, _c16 = (_u & 7) * 16; \
            CP_ASYNC16(_as + SMEM_SWIZZLE_128B(_r * 128 + _c16), \
                       Abase + (size_t)_r * ROWB + _ko + _c16); \
        } \
        _Pragma("unroll") \
        for (int _i = 0; _i < 4; _i++) { \
            int _u = tid + _i * 256; \
            int _r = _u >> 3, _c16 = (_u & 7) * 16; \
            CP_ASYNC16(_bs + SMEM_SWIZZLE_128B(_r * 128 + _c16), \
                       Bbase + (size_t)_r * ROWB + _ko + _c16); \
        } \
        CP_ASYNC_COMMIT(); \
    } while (0)

    #define MMA_CHUNK(Astage, Bstage) do { \
        uint32_t _As = sb + (Astage) * GEMM_STAGE; \
        uint32_t _Bs = sb + (Bstage) * GEMM_STAGE + 16384; \
        _Pragma("unroll") \
        for (int kk = 0; kk < 4; kk++) { \
            uint32_t a[4][4]; \
            _Pragma("unroll") \
            for (int mi = 0; mi < 4; mi++) { \
                int row = wm * 64 + mi * 16 + (lane & 15); \
                int u   = kk * 2 + (lane >> 4); \
                ldsm_x4(a[mi][0], a[mi][1], a[mi][2], a[mi][3], \
                        _As + row * 128 + ((u ^ (row & 7)) << 4)); \
            } \
            uint32_t bf[2][4]; \
            _Pragma("unroll") \
            for (int nf = 0; nf < 2; nf++) { \
                int row = wn * 32 + nf * 16 + ((lane >> 4) << 3) + (lane & 7); \
                int u   = kk * 2 + ((lane >> 3) & 1); \
                ldsm_x4(bf[nf][0], bf[nf][1], bf[nf][2], bf[nf][3], \
                        _Bs + row * 128 + ((u ^ (row & 7)) << 4)); \
            } \
            _Pragma("unroll") \
            for (int mi = 0; mi < 4; mi++) \
                _Pragma("unroll") \
                for (int nj = 0; nj < 4; nj++) \
                    mma16816(acc[mi * 4 + nj], \
                             a[mi][0], a[mi][1], a[mi][2], a[mi][3], \
                             bf[nj >> 1][(nj & 1) * 2], bf[nj >> 1][(nj & 1) * 2 + 1]); \
        } \
    } while (0)

    GLOAD(0); GLOAD(1); GLOAD(2);

    #pragma unroll
    for (int g = 0; g < 8; g++) {
        const int sA = (2 * g) % 3;
        const int sB = (2 * g + 1) % 3;

        if (g == 0) asm volatile("cp.async.wait_group 2;" ::: "memory");
        else        asm volatile("cp.async.wait_group 0;" ::: "memory");
        __syncthreads();
        if (g >= 1) {
            GLOAD(2 * g + 1);
            if (2 * g + 2 <= 15) GLOAD(2 * g + 2);
        }
        MMA_CHUNK(sA, sA);

        if (g == 7) asm volatile("cp.async.wait_group 0;" ::: "memory");
        else        asm volatile("cp.async.wait_group 1;" ::: "memory");
        __syncthreads();
        MMA_CHUNK(sB, sA);

        MMA_CHUNK(sA, sB);
    }
    #undef GLOAD
    #undef MMA_CHUNK
}

// ===================== merged prep kernel ===================================
// bx < 2048            : cb split
// 2048 <= bx < 2816    : Wq/Wk/Wv transpose-split (vectorized stores)
// 2816 <= bx < 3072    : hidden transpose-split + fused head gates (vectorized)
__global__ void prep_all_kernel(const float* __restrict__ cb,
                                const float* __restrict__ Wq,
                                const float* __restrict__ Wk,
                                const float* __restrict__ Wv,
                                const float* __restrict__ hidden,
                                const float* __restrict__ Wp,
                                const float* __restrict__ bp) {
    __shared__ float tile[32][33];
    __shared__ float sWp[CDIM * HH];
    int bx = blockIdx.x;
    if (bx < 2048) {
        int idx = bx * 256 + threadIdx.x;
        int n  = idx >> 7;
        int c4 = (idx & 127) * 4;
        float4 v = *(const float4*)(cb + (size_t)n * CDIM + c4);
        unsigned h0, l0, h1, l1;
        split2bf(v.x, v.y, h0, l0);
        split2bf(v.z, v.w, h1, l1);
        __nv_bfloat16* op = g_AcbS + (size_t)n * KPHYS + c4;
        *(uint2*)(op)       = make_uint2(h0, h1);
        *(uint2*)(op + 512) = make_uint2(l0, l1);
    } else if (bx < 2816) {
        int bid = bx - 2048;          // 0..767
        int z   = bid >> 8;           // 0..2
        int rem = bid & 255;
        int ci0 = (rem >> 4) * 32, c0 = (rem & 15) * 32;
        const float* W = (z == 0) ? Wq : (z == 1) ? Wk : Wv;
        int tx = threadIdx.x & 31, ty = threadIdx.x >> 5;
        #pragma unroll
        for (int k = 0; k < 4; k++)
            tile[ty + 8 * k][tx] = W[(size_t)(ci0 + ty + 8 * k) * CDIM + c0 + tx];
        __syncthreads();
        __nv_bfloat16* base = g_WTS[z];
        // vectorized: lane pair-structure: m = lane&15 covers ci pair 2m,2m+1;
        // khalf = lane>>4 picks the k-subgroup; kk iterates 2.
        int m = tx & 15, khalf = tx >> 4;
        #pragma unroll
        for (int kk = 0; kk < 2; kk++) {
            int y = ty + 8 * (2 * kk + khalf);        // 0..31
            int c = c0 + y;
            float v0 = tile[2 * m][y], v1 = tile[2 * m + 1][y];
            unsigned hu, lu;
            split2bf(v0, v1, hu, lu);
            __nv_bfloat16* op = base + (size_t)c * KPHYS + ci0 + 2 * m;
            *(unsigned*)(op)       = hu;
            *(unsigned*)(op + 512) = lu;
        }
    } else {
        int r  = bx - 2816;           // 0..255
        int b  = r >> 6;
        int t0 = (r & 63) * 32;
        int tx = threadIdx.x & 31, ty = threadIdx.x >> 5;
        const float* hp = hidden + (size_t)b * CDIM * TDIM;

        #pragma unroll
        for (int i = 0; i < 8; i++)
            sWp[threadIdx.x + i * 256] = Wp[threadIdx.x + i * 256];

        float cgacc = 0.f;
        int tl = threadIdx.x >> 2, hh = threadIdx.x & 3;
        int m = tx & 15, khalf = tx >> 4;

        for (int ci0 = 0; ci0 < CDIM; ci0 += 32) {
            __syncthreads();
            #pragma unroll
            for (int k = 0; k < 4; k++)
                tile[ty + 8 * k][tx] = hp[(size_t)(ci0 + ty + 8 * k) * TDIM + t0 + tx];
            __syncthreads();
            // vectorized transposed split store (tile[ci][t] layout)
            #pragma unroll
            for (int kk = 0; kk < 2; kk++) {
                int y = ty + 8 * (2 * kk + khalf);    // t-local 0..31
                int t = t0 + y;
                float v0 = tile[2 * m][y], v1 = tile[2 * m + 1][y];
                unsigned hu, lu;
                split2bf(v0, v1, hu, lu);
                __nv_bfloat16* op = g_HsS + ((size_t)b * TDIM + t) * KPHYS + ci0 + 2 * m;
                *(unsigned*)(op)       = hu;
                *(unsigned*)(op + 512) = lu;
            }
            if (threadIdx.x < 128) {
                #pragma unroll 8
                for (int ci = 0; ci < 32; ci++)
                    cgacc += tile[ci][tl] * sWp[(ci0 + ci) * 4 + hh];
            }
        }
        if (threadIdx.x < 128) {
            int bt = b * TDIM + t0 + tl;
            g_cg[(size_t)bt * 4 + hh] = cgacc + bp[hh];
        }
    }
}

// ===================== merged projection GEMMs (tensor) =====================
__global__ __launch_bounds__(256, 2)
void gemm_proj_all(const float* __restrict__ bq, const float* __restrict__ bk,
                   const float* __restrict__ bv) {
    extern __shared__ __align__(1024) char smem[];
    const int tid = threadIdx.x;
    const int lane = tid & 31, wid = tid >> 5;
    const int wm = wid & 1, wn = wid >> 1;
    const int y = blockIdx.y;
    const int cBase = blockIdx.x * 128;
    const uint32_t sb = smem_to_u32(smem);

    const char* Abase;
    const char* Bbase;
    int rBase;
    int mode;           // 0=K', 1=V, 2=Qg
    if (y < 32)       { mode = 0; rBase = y * 128;
                        Abase = (const char*)(g_AcbS + (size_t)rBase * KPHYS);
                        Bbase = (const char*)(g_WTS[1] + (size_t)cBase * KPHYS); }
    else if (y < 64)  { mode = 1; rBase = (y - 32) * 128;
                        Abase = (const char*)(g_AcbS + (size_t)rBase * KPHYS);
                        Bbase = (const char*)(g_WTS[2] + (size_t)cBase * KPHYS); }
    else              { mode = 2; rBase = (y - 64) * 128;
                        Abase = (const char*)(g_HsS + (size_t)rBase * KPHYS);
                        Bbase = (const char*)(g_WTS[0] + (size_t)cBase * KPHYS); }

    float acc[16][4] = {};
    gemm1536_core(Abase, Bbase, sb, tid, acc);

    if (mode == 0) {
        #pragma unroll
        for (int mi = 0; mi < 4; mi++)
            #pragma unroll
            for (int nj = 0; nj < 4; nj++) {
                float* A = acc[mi * 4 + nj];
                int r  = wm * 64 + mi * 16 + (lane >> 2);
                int cc = cBase + wn * 32 + nj * 8 + 2 * (lane & 3);
                float b0 = bk[cc], b1 = bk[cc + 1];
                unsigned h, l;
                split2bf(A[0] + b0, A[1] + b1, h, l);
                __nv_bfloat16* op = g_KpS + (size_t)(rBase + r) * KPHYS + cc;
                *(unsigned*)(op) = h; *(unsigned*)(op + 512) = l;
                split2bf(A[2] + b0, A[3] + b1, h, l);
                op = g_KpS + (size_t)(rBase + r + 8) * KPHYS + cc;
                *(unsigned*)(op) = h; *(unsigned*)(op + 512) = l;
            }
    } else if (mode == 1) {
        #pragma unroll
        for (int mi = 0; mi < 4; mi++)
            #pragma unroll
            for (int nj = 0; nj < 4; nj++) {
                float* A = acc[mi * 4 + nj];
                int r  = wm * 64 + mi * 16 + (lane >> 2);
                int cc = cBase + wn * 32 + nj * 8 + 2 * (lane & 3);
                float b0 = bv[cc], b1 = bv[cc + 1];
                *(float2*)(g_V + (size_t)(rBase + r) * CDIM + cc) =
                    make_float2(A[0] + b0, A[1] + b1);
                *(float2*)(g_V + (size_t)(rBase + r + 8) * CDIM + cc) =
                    make_float2(A[2] + b0, A[3] + b1);
            }
    } else {
        const int h = blockIdx.x;
        #pragma unroll
        for (int mi = 0; mi < 4; mi++)
            #pragma unroll
            for (int nj = 0; nj < 4; nj++) {
                float* A = acc[mi * 4 + nj];
                int r  = wm * 64 + mi * 16 + (lane >> 2);
                int cc = cBase + wn * 32 + nj * 8 + 2 * (lane & 3);
                float b0 = bq[cc], b1 = bq[cc + 1];
                int bt0 = rBase + r, bt1 = rBase + r + 8;
                float g0 = g_cg[(size_t)bt0 * 4 + h] * CSCALE;
                float g1 = g_cg[(size_t)bt1 * 4 + h] * CSCALE;
                unsigned hh, ll;
                split2bf((A[0] + b0) * g0, (A[1] + b1) * g0, hh, ll);
                __nv_bfloat16* op = g_QgS + (size_t)bt0 * KPHYS + cc;
                *(unsigned*)(op) = hh; *(unsigned*)(op + 512) = ll;
                split2bf((A[2] + b0) * g1, (A[3] + b1) * g1, hh, ll);
                op = g_QgS + (size_t)bt1 * KPHYS + cc;
                *(unsigned*)(op) = hh; *(unsigned*)(op + 512) = ll;
            }
    }
}

// ===================== logits GEMM + fused argmax partials ==================
__global__ __launch_bounds__(256, 2)
void gemm_logits_mma(float* __restrict__ out) {
    extern __shared__ __align__(1024) char smem[];
    const int tid  = threadIdx.x;
    const int wid  = tid >> 5, lane = tid & 31;
    const int wm   = wid & 1;
    const int wn   = wid >> 1;
    const int b     = blockIdx.z;
    const int nBase = blockIdx.y * 128;
    const int tBase = blockIdx.x * 128;
    const uint32_t sb = smem_to_u32(smem);

    float acc[16][4] = {};
    gemm1536_core((const char*)(g_KpS + (size_t)nBase * KPHYS),
                  (const char*)(g_QgS + ((size_t)b * TDIM + tBase) * KPHYS),
                  sb, tid, acc);

    __syncthreads();   // smem free; safe to alias for argmax below

    // ---- write logits ----
    float* obase = out + (size_t)b * NCB * TDIM + (size_t)nBase * TDIM + tBase;
    #pragma unroll
    for (int mi = 0; mi < 4; mi++) {
        #pragma unroll
        for (int nj = 0; nj < 4; nj++) {
            float* A = acc[mi * 4 + nj];
            int r  = wm * 64 + mi * 16 + (lane >> 2);
            int cc = wn * 32 + nj * 8 + 2 * (lane & 3);
            *(float2*)(obase + (size_t)r * TDIM + cc)       = make_float2(A[0], A[1]);
            *(float2*)(obase + (size_t)(r + 8) * TDIM + cc) = make_float2(A[2], A[3]);
        }
    }

    // ---- fused argmax partial over this CTA's 128 rows ----
    float mv[8]; int mi_[8];
    #pragma unroll
    for (int nj = 0; nj < 4; nj++) {
        #pragma unroll
        for (int cc = 0; cc < 2; cc++) {
            int key = nj * 2 + cc;
            float best = -INFINITY; int bidx = 0;
            #pragma unroll
            for (int mi = 0; mi < 4; mi++) {
                #pragma unroll
                for (int hf = 0; hf < 2; hf++) {
                    float v = acc[mi * 4 + nj][hf * 2 + cc];
                    int   ix = nBase + wm * 64 + mi * 16 + (lane >> 2) + hf * 8;
                    if (v > best || (v == best && ix < bidx)) { best = v; bidx = ix; }
                }
            }
            mv[key] = best; mi_[key] = bidx;
        }
    }
    #pragma unroll
    for (int off = 4; off < 32; off <<= 1) {
        #pragma unroll
        for (int key = 0; key < 8; key++) {
            float ov = __shfl_xor_sync(0xffffffff, mv[key], off);
            int   oi = __shfl_xor_sync(0xffffffff, mi_[key], off);
            if (ov > mv[key] || (ov == mv[key] && oi < mi_[key])) {
                mv[key] = ov; mi_[key] = oi;
            }
        }
    }
    float* sval = (float*)smem;               // [2][128]
    int*   sidx = (int*)(smem + 2 * 128 * 4); // [2][128]
    if (lane < 4) {
        #pragma unroll
        for (int nj = 0; nj < 4; nj++)
            #pragma unroll
            for (int cc = 0; cc < 2; cc++) {
                int col = wn * 32 + nj * 8 + 2 * lane + cc;
                sval[wm * 128 + col] = mv[nj * 2 + cc];
                sidx[wm * 128 + col] = mi_[nj * 2 + cc];
            }
    }
    __syncthreads();
    if (tid < 128) {
        float v0 = sval[tid],      v1 = sval[128 + tid];
        int   i0 = sidx[tid],      i1 = sidx[128 + tid];
        bool take1 = (v1 > v0) || (v1 == v0 && i1 < i0);
        size_t o = ((size_t)blockIdx.y * BATCH + b) * TDIM + tBase + tid;
        g_pmax[o] = take1 ? v1 : v0;
        g_pidx[o] = take1 ? i1 : i0;
    }
}

// ------ fused final argmax (32 slices) + smem-staged z_q gather -------------
#define ZQ_PITCH 517
#define ZQ_SMEM  (32 * ZQ_PITCH * 4)     // 66176 B

__global__ void argmax_zq_kernel(float* __restrict__ idx_out, float* __restrict__ zq) {
    extern __shared__ float sV[];            // [32][ZQ_PITCH]
    __shared__ int sIdx[32];
    int b = blockIdx.y;
    int t0 = blockIdx.x * 32;
    int lane = threadIdx.x & 31;
    int wid  = threadIdx.x >> 5;

    if (threadIdx.x < 32) {
        int t = t0 + threadIdx.x;
        float best = -INFINITY; int bi = 0x7fffffff;
        #pragma unroll
        for (int z = 0; z < NBLOCKS; z++) {
            float x = g_pmax[((size_t)z * BATCH + b) * TDIM + t];
            int  ii = g_pidx[((size_t)z * BATCH + b) * TDIM + t];
            if (x > best || (x == best && ii < bi)) { best = x; bi = ii; }
        }
        g_idx[b * TDIM + t] = bi;
        sIdx[threadIdx.x] = bi;
        idx_out[b * TDIM + t] = (float)bi;
    }
    __syncthreads();

    // Phase B: each warp stages 4 rows (t-local = wid, wid+8, wid+16, wid+24)
    #pragma unroll
    for (int r4 = 0; r4 < 4; r4++) {
        int tl = wid + r4 * 8;
        const float* v = g_V + (size_t)sIdx[tl] * CDIM;
        #pragma unroll
        for (int k = 0; k < CDIM / 32; k++)
            sV[tl * ZQ_PITCH + k * 32 + lane] = __ldg(&v[k * 32 + lane]);
    }
    __syncthreads();

    // Phase C: cgrp covers 64 c's; lanes give consecutive t -> 128B stores.
    int cgrp = wid;
    float* o = zq + (size_t)b * CDIM * TDIM + t0 + lane;
    int c0 = cgrp * 64;
    #pragma unroll 8
    for (int c = c0; c < c0 + 64; c++)
        o[(size_t)c * TDIM] = sV[lane * ZQ_PITCH + c];
}

// ---------------- launcher --------------------------------------------------
extern "C" void kernel_launch(void* const* d_in, const int* in_sizes, int n_in,
                              void* d_out, int out_size) {
    const float* hidden = (const float*)d_in[0];  // [B,C,T]
    const float* cb     = (const float*)d_in[1];  // [N,C]
    const float* Wq = (const float*)d_in[2]; const float* bq = (const float*)d_in[3];
    const float* Wk = (const float*)d_in[4]; const float* bk = (const float*)d_in[5];
    const float* Wv = (const float*)d_in[6]; const float* bv = (const float*)d_in[7];
    const float* Wp = (const float*)d_in[8]; const float* bp = (const float*)d_in[9];

    float* out        = (float*)d_out;
    float* out_logits = out;                                       // B*N*T
    float* out_idx    = out + (size_t)BATCH * NCB * TDIM;          // B*T
    float* out_zq     = out_idx + (size_t)BATCH * TDIM;            // B*C*T

    cudaFuncSetAttribute(gemm_proj_all,
                         cudaFuncAttributeMaxDynamicSharedMemorySize, GEMM_SMEM);
    cudaFuncSetAttribute(gemm_logits_mma,
                         cudaFuncAttributeMaxDynamicSharedMemorySize, GEMM_SMEM);
    cudaFuncSetAttribute(argmax_zq_kernel,
                         cudaFuncAttributeMaxDynamicSharedMemorySize, ZQ_SMEM);

    // all prep (cb split, W splits, hidden split + cg)
    prep_all_kernel<<<3072, 256>>>(cb, Wq, Wk, Wv, hidden, Wp, bp);
    // all projections in one launch (tile 128x128)
    gemm_proj_all<<<dim3(4, 128), 256, GEMM_SMEM>>>(bq, bk, bv);
    // logits + fused argmax partials
    gemm_logits_mma<<<dim3(TDIM / 128, NCB / 128, BATCH), 256, GEMM_SMEM>>>(out_logits);
    // fused final argmax + smem-staged z_q gather
    argmax_zq_kernel<<<dim3(TDIM / 32, BATCH), 256, ZQ_SMEM>>>(out_idx, out_zq);
}

// round 17
// speedup vs baseline: 1.5950x; 1.0439x over previous
#include <cuda_runtime.h>
#include <cuda_bf16.h>
#include <math.h>
#include <stdint.h>

// Problem constants
#define BATCH 4
#define CDIM  512
#define TDIM  2048
#define NCB   4096
#define HH    4
// Physical split storage: [hi|lo] = 1024 bf16 = 2048 B per row.
// Logical K = 1536: products Ah*Bh + Al*Bh + Ah*Bl per 64-col ci-group.
#define KPHYS 1024
#define ROWB  2048
#define CSCALE 0.04419417382415922f   // 1/(sqrt(128)*sqrt(4))

#define NBLOCKS (NCB / 128)        // 32 partial-argmax slices

// ---------------- scratch (device globals; no runtime allocation) -----------
__device__ __nv_bfloat16 g_AcbS[(size_t)NCB * KPHYS];          // cb split [hi|lo]
__device__ __nv_bfloat16 g_HsS [(size_t)BATCH * TDIM * KPHYS]; // hs^T split [hi|lo]
__device__ __nv_bfloat16 g_WTS [3][(size_t)CDIM * KPHYS];      // Wq,Wk,Wv^T [hi|lo]
__device__ __nv_bfloat16 g_KpS[(size_t)NCB * KPHYS];           // K' split [hi|lo]
__device__ __nv_bfloat16 g_QgS[(size_t)BATCH * TDIM * KPHYS];  // Qg split [hi|lo]
__device__ float g_V [(size_t)NCB * CDIM];
__device__ float g_cgp[4][(size_t)BATCH * TDIM * HH];  // head-gate partials (no bias)
__device__ int   g_idx[(size_t)BATCH * TDIM];
__device__ float g_pmax[NBLOCKS * BATCH * TDIM];
__device__ int   g_pidx[NBLOCKS * BATCH * TDIM];

// ======================= helpers ============================================
#define SMEM_SWIZZLE_128B(off) ((off) ^ (((off) >> 3) & 0x70))
#define CP_ASYNC16(dst, src) \
    asm volatile("cp.async.cg.shared.global [%0], [%1], 16;" :: "r"(dst), "l"(src))
#define CP_ASYNC_COMMIT() asm volatile("cp.async.commit_group;" ::: "memory")

__device__ __forceinline__ uint32_t smem_to_u32(const void* p) {
    uint32_t a;
    asm("{ .reg .u64 t; cvta.to.shared.u64 t, %1; cvt.u32.u64 %0, t; }"
        : "=r"(a) : "l"(p));
    return a;
}
__device__ __forceinline__ void ldsm_x4(uint32_t& r0, uint32_t& r1, uint32_t& r2,
                                        uint32_t& r3, uint32_t addr) {
    asm volatile("ldmatrix.sync.aligned.m8n8.x4.shared.b16 {%0,%1,%2,%3}, [%4];"
                 : "=r"(r0), "=r"(r1), "=r"(r2), "=r"(r3) : "r"(addr));
}
__device__ __forceinline__ void mma16816(float* c, uint32_t a0, uint32_t a1,
                                         uint32_t a2, uint32_t a3,
                                         uint32_t b0, uint32_t b1) {
    asm volatile(
        "mma.sync.aligned.m16n8k16.row.col.f32.bf16.bf16.f32 "
        "{%0,%1,%2,%3}, {%4,%5,%6,%7}, {%8,%9}, {%0,%1,%2,%3};"
        : "+f"(c[0]), "+f"(c[1]), "+f"(c[2]), "+f"(c[3])
        : "r"(a0), "r"(a1), "r"(a2), "r"(a3), "r"(b0), "r"(b1));
}
__device__ __forceinline__ void split2bf(float v0, float v1, unsigned& hu, unsigned& lu) {
    __nv_bfloat16 h0 = __float2bfloat16(v0), h1 = __float2bfloat16(v1);
    float r0 = v0 - __bfloat162float(h0), r1 = v1 - __bfloat162float(h1);
    __nv_bfloat16 l0 = __float2bfloat16(r0), l1 = __float2bfloat16(r1);
    __nv_bfloat162 ph = __halves2bfloat162(h0, h1);
    __nv_bfloat162 pl = __halves2bfloat162(l0, l1);
    hu = *reinterpret_cast<unsigned*>(&ph);
    lu = *reinterpret_cast<unsigned*>(&pl);
}

// ====== canonical logical-K=1536 bf16 mma core with tile reuse ==============
// (R9 core: 16 loads, 24 MMA chunks, 2 syncs/group)
#define GEMM_STAGE  32768                    // A 16KB + B 16KB
#define GEMM_SMEM   (3 * GEMM_STAGE)         // 98304

__device__ __forceinline__ void gemm1536_core(const char* Abase, const char* Bbase,
                                              uint32_t sb, int tid,
                                              float (&acc)[16][4]) {
    const int lane = tid & 31;
    const int wid  = tid >> 5;
    const int wm = wid & 1, wn = wid >> 1;

    #define GLOAD(j) do { \
        uint32_t _as = sb + ((j) % 3) * GEMM_STAGE; \
        uint32_t _bs = _as + 16384; \
        size_t _ko = (size_t)(((j) & 1) ? 8 + ((j) >> 1) : ((j) >> 1)) * 128; \
        _Pragma("unroll") \
        for (int _i = 0; _i < 4; _i++) { \
            int _u = tid + _i * 256; \
            int _r = _u >> 3, _c16 = (_u & 7) * 16; \
            CP_ASYNC16(_as + SMEM_SWIZZLE_128B(_r * 128 + _c16), \
                       Abase + (size_t)_r * ROWB + _ko + _c16); \
        } \
        _Pragma("unroll") \
        for (int _i = 0; _i < 4; _i++) { \
            int _u = tid + _i * 256; \
            int _r = _u >> 3, _c16 = (_u & 7) * 16; \
            CP_ASYNC16(_bs + SMEM_SWIZZLE_128B(_r * 128 + _c16), \
                       Bbase + (size_t)_r * ROWB + _ko + _c16); \
        } \
        CP_ASYNC_COMMIT(); \
    } while (0)

    #define MMA_CHUNK(Astage, Bstage) do { \
        uint32_t _As = sb + (Astage) * GEMM_STAGE; \
        uint32_t _Bs = sb + (Bstage) * GEMM_STAGE + 16384; \
        _Pragma("unroll") \
        for (int kk = 0; kk < 4; kk++) { \
            uint32_t a[4][4]; \
            _Pragma("unroll") \
            for (int mi = 0; mi < 4; mi++) { \
                int row = wm * 64 + mi * 16 + (lane & 15); \
                int u   = kk * 2 + (lane >> 4); \
                ldsm_x4(a[mi][0], a[mi][1], a[mi][2], a[mi][3], \
                        _As + row * 128 + ((u ^ (row & 7)) << 4)); \
            } \
            uint32_t bf[2][4]; \
            _Pragma("unroll") \
            for (int nf = 0; nf < 2; nf++) { \
                int row = wn * 32 + nf * 16 + ((lane >> 4) << 3) + (lane & 7); \
                int u   = kk * 2 + ((lane >> 3) & 1); \
                ldsm_x4(bf[nf][0], bf[nf][1], bf[nf][2], bf[nf][3], \
                        _Bs + row * 128 + ((u ^ (row & 7)) << 4)); \
            } \
            _Pragma("unroll") \
            for (int mi = 0; mi < 4; mi++) \
                _Pragma("unroll") \
                for (int nj = 0; nj < 4; nj++) \
                    mma16816(acc[mi * 4 + nj], \
                             a[mi][0], a[mi][1], a[mi][2], a[mi][3], \
                             bf[nj >> 1][(nj & 1) * 2], bf[nj >> 1][(nj & 1) * 2 + 1]); \
        } \
    } while (0)

    GLOAD(0); GLOAD(1); GLOAD(2);

    #pragma unroll
    for (int g = 0; g < 8; g++) {
        const int sA = (2 * g) % 3;
        const int sB = (2 * g + 1) % 3;

        if (g == 0) asm volatile("cp.async.wait_group 2;" ::: "memory");
        else        asm volatile("cp.async.wait_group 0;" ::: "memory");
        __syncthreads();
        if (g >= 1) {
            GLOAD(2 * g + 1);
            if (2 * g + 2 <= 15) GLOAD(2 * g + 2);
        }
        MMA_CHUNK(sA, sA);

        if (g == 7) asm volatile("cp.async.wait_group 0;" ::: "memory");
        else        asm volatile("cp.async.wait_group 1;" ::: "memory");
        __syncthreads();
        MMA_CHUNK(sB, sA);

        MMA_CHUNK(sA, sB);
    }
    #undef GLOAD
    #undef MMA_CHUNK
}

// ===================== merged prep kernel ===================================
// bx < 2048            : cb split
// 2048 <= bx < 2816    : Wq/Wk/Wv transpose-split (vectorized stores)
// 2816 <= bx < 3840    : hidden transpose-split (ci-quartered) + cg partials
__global__ void prep_all_kernel(const float* __restrict__ cb,
                                const float* __restrict__ Wq,
                                const float* __restrict__ Wk,
                                const float* __restrict__ Wv,
                                const float* __restrict__ hidden,
                                const float* __restrict__ Wp) {
    __shared__ float tile[32][33];
    __shared__ float sWp[128 * HH];
    int bx = blockIdx.x;
    if (bx < 2048) {
        int idx = bx * 256 + threadIdx.x;
        int n  = idx >> 7;
        int c4 = (idx & 127) * 4;
        float4 v = *(const float4*)(cb + (size_t)n * CDIM + c4);
        unsigned h0, l0, h1, l1;
        split2bf(v.x, v.y, h0, l0);
        split2bf(v.z, v.w, h1, l1);
        __nv_bfloat16* op = g_AcbS + (size_t)n * KPHYS + c4;
        *(uint2*)(op)       = make_uint2(h0, h1);
        *(uint2*)(op + 512) = make_uint2(l0, l1);
    } else if (bx < 2816) {
        int bid = bx - 2048;          // 0..767
        int z   = bid >> 8;           // 0..2
        int rem = bid & 255;
        int ci0 = (rem >> 4) * 32, c0 = (rem & 15) * 32;
        const float* W = (z == 0) ? Wq : (z == 1) ? Wk : Wv;
        int tx = threadIdx.x & 31, ty = threadIdx.x >> 5;
        #pragma unroll
        for (int k = 0; k < 4; k++)
            tile[ty + 8 * k][tx] = W[(size_t)(ci0 + ty + 8 * k) * CDIM + c0 + tx];
        __syncthreads();
        __nv_bfloat16* base = g_WTS[z];
        int m = tx & 15, khalf = tx >> 4;
        #pragma unroll
        for (int kk = 0; kk < 2; kk++) {
            int y = ty + 8 * (2 * kk + khalf);        // 0..31
            int c = c0 + y;
            float v0 = tile[2 * m][y], v1 = tile[2 * m + 1][y];
            unsigned hu, lu;
            split2bf(v0, v1, hu, lu);
            __nv_bfloat16* op = base + (size_t)c * KPHYS + ci0 + 2 * m;
            *(unsigned*)(op)       = hu;
            *(unsigned*)(op + 512) = lu;
        }
    } else {
        int r  = bx - 2816;           // 0..1023
        int q  = r & 3;               // ci quarter 0..3
        int tb = r >> 2;              // 0..255
        int b  = tb >> 6;
        int t0 = (tb & 63) * 32;
        int tx = threadIdx.x & 31, ty = threadIdx.x >> 5;
        const float* hp = hidden + (size_t)b * CDIM * TDIM;
        const int ciBase = q * 128;

        // Wp slice for this quarter: [128 ci][4 h]
        #pragma unroll
        for (int i = 0; i < 2; i++)
            sWp[threadIdx.x + i * 256] = Wp[(size_t)ciBase * HH + threadIdx.x + i * 256];

        float cgacc = 0.f;
        int tl = threadIdx.x >> 2, hh = threadIdx.x & 3;
        int m = tx & 15, khalf = tx >> 4;

        for (int cio = 0; cio < 128; cio += 32) {
            int ci0 = ciBase + cio;
            __syncthreads();
            #pragma unroll
            for (int k = 0; k < 4; k++)
                tile[ty + 8 * k][tx] = hp[(size_t)(ci0 + ty + 8 * k) * TDIM + t0 + tx];
            __syncthreads();
            // vectorized transposed split store (tile[ci][t] layout)
            #pragma unroll
            for (int kk = 0; kk < 2; kk++) {
                int y = ty + 8 * (2 * kk + khalf);    // t-local 0..31
                int t = t0 + y;
                float v0 = tile[2 * m][y], v1 = tile[2 * m + 1][y];
                unsigned hu, lu;
                split2bf(v0, v1, hu, lu);
                __nv_bfloat16* op = g_HsS + ((size_t)b * TDIM + t) * KPHYS + ci0 + 2 * m;
                *(unsigned*)(op)       = hu;
                *(unsigned*)(op + 512) = lu;
            }
            if (threadIdx.x < 128) {
                #pragma unroll 8
                for (int ci = 0; ci < 32; ci++)
                    cgacc += tile[ci][tl] * sWp[(cio + ci) * 4 + hh];
            }
        }
        if (threadIdx.x < 128) {
            size_t bt = (size_t)b * TDIM + t0 + tl;
            g_cgp[q][bt * 4 + hh] = cgacc;
        }
    }
}

// ===================== merged projection GEMMs (tensor) =====================
__global__ __launch_bounds__(256, 2)
void gemm_proj_all(const float* __restrict__ bq, const float* __restrict__ bk,
                   const float* __restrict__ bv, const float* __restrict__ bp) {
    extern __shared__ __align__(1024) char smem[];
    const int tid = threadIdx.x;
    const int lane = tid & 31, wid = tid >> 5;
    const int wm = wid & 1, wn = wid >> 1;
    const int y = blockIdx.y;
    const int cBase = blockIdx.x * 128;
    const uint32_t sb = smem_to_u32(smem);

    const char* Abase;
    const char* Bbase;
    int rBase;
    int mode;           // 0=K', 1=V, 2=Qg
    if (y < 32)       { mode = 0; rBase = y * 128;
                        Abase = (const char*)(g_AcbS + (size_t)rBase * KPHYS);
                        Bbase = (const char*)(g_WTS[1] + (size_t)cBase * KPHYS); }
    else if (y < 64)  { mode = 1; rBase = (y - 32) * 128;
                        Abase = (const char*)(g_AcbS + (size_t)rBase * KPHYS);
                        Bbase = (const char*)(g_WTS[2] + (size_t)cBase * KPHYS); }
    else              { mode = 2; rBase = (y - 64) * 128;
                        Abase = (const char*)(g_HsS + (size_t)rBase * KPHYS);
                        Bbase = (const char*)(g_WTS[0] + (size_t)cBase * KPHYS); }

    float acc[16][4] = {};
    gemm1536_core(Abase, Bbase, sb, tid, acc);

    if (mode == 0) {
        #pragma unroll
        for (int mi = 0; mi < 4; mi++)
            #pragma unroll
            for (int nj = 0; nj < 4; nj++) {
                float* A = acc[mi * 4 + nj];
                int r  = wm * 64 + mi * 16 + (lane >> 2);
                int cc = cBase + wn * 32 + nj * 8 + 2 * (lane & 3);
                float b0 = bk[cc], b1 = bk[cc + 1];
                unsigned h, l;
                split2bf(A[0] + b0, A[1] + b1, h, l);
                __nv_bfloat16* op = g_KpS + (size_t)(rBase + r) * KPHYS + cc;
                *(unsigned*)(op) = h; *(unsigned*)(op + 512) = l;
                split2bf(A[2] + b0, A[3] + b1, h, l);
                op = g_KpS + (size_t)(rBase + r + 8) * KPHYS + cc;
                *(unsigned*)(op) = h; *(unsigned*)(op + 512) = l;
            }
    } else if (mode == 1) {
        #pragma unroll
        for (int mi = 0; mi < 4; mi++)
            #pragma unroll
            for (int nj = 0; nj < 4; nj++) {
                float* A = acc[mi * 4 + nj];
                int r  = wm * 64 + mi * 16 + (lane >> 2);
                int cc = cBase + wn * 32 + nj * 8 + 2 * (lane & 3);
                float b0 = bv[cc], b1 = bv[cc + 1];
                *(float2*)(g_V + (size_t)(rBase + r) * CDIM + cc) =
                    make_float2(A[0] + b0, A[1] + b1);
                *(float2*)(g_V + (size_t)(rBase + r + 8) * CDIM + cc) =
                    make_float2(A[2] + b0, A[3] + b1);
            }
    } else {
        const int h = blockIdx.x;
        const float bph = bp[h];
        #pragma unroll
        for (int mi = 0; mi < 4; mi++)
            #pragma unroll
            for (int nj = 0; nj < 4; nj++) {
                float* A = acc[mi * 4 + nj];
                int r  = wm * 64 + mi * 16 + (lane >> 2);
                int cc = cBase + wn * 32 + nj * 8 + 2 * (lane & 3);
                float b0 = bq[cc], b1 = bq[cc + 1];
                size_t bt0 = (size_t)rBase + r, bt1 = (size_t)rBase + r + 8;
                float cg0 = g_cgp[0][bt0 * 4 + h] + g_cgp[1][bt0 * 4 + h]
                          + g_cgp[2][bt0 * 4 + h] + g_cgp[3][bt0 * 4 + h] + bph;
                float cg1 = g_cgp[0][bt1 * 4 + h] + g_cgp[1][bt1 * 4 + h]
                          + g_cgp[2][bt1 * 4 + h] + g_cgp[3][bt1 * 4 + h] + bph;
                float g0 = cg0 * CSCALE;
                float g1 = cg1 * CSCALE;
                unsigned hh, ll;
                split2bf((A[0] + b0) * g0, (A[1] + b1) * g0, hh, ll);
                __nv_bfloat16* op = g_QgS + bt0 * KPHYS + cc;
                *(unsigned*)(op) = hh; *(unsigned*)(op + 512) = ll;
                split2bf((A[2] + b0) * g1, (A[3] + b1) * g1, hh, ll);
                op = g_QgS + bt1 * KPHYS + cc;
                *(unsigned*)(op) = hh; *(unsigned*)(op + 512) = ll;
            }
    }
}

// ===================== logits GEMM + fused argmax partials ==================
__global__ __launch_bounds__(256, 2)
void gemm_logits_mma(float* __restrict__ out) {
    extern __shared__ __align__(1024) char smem[];
    const int tid  = threadIdx.x;
    const int wid  = tid >> 5, lane = tid & 31;
    const int wm   = wid & 1;
    const int wn   = wid >> 1;
    const int b     = blockIdx.z;
    const int nBase = blockIdx.y * 128;
    const int tBase = blockIdx.x * 128;
    const uint32_t sb = smem_to_u32(smem);

    float acc[16][4] = {};
    gemm1536_core((const char*)(g_KpS + (size_t)nBase * KPHYS),
                  (const char*)(g_QgS + ((size_t)b * TDIM + tBase) * KPHYS),
                  sb, tid, acc);

    __syncthreads();   // smem free; safe to alias for argmax below

    // ---- write logits ----
    float* obase = out + (size_t)b * NCB * TDIM + (size_t)nBase * TDIM + tBase;
    #pragma unroll
    for (int mi = 0; mi < 4; mi++) {
        #pragma unroll
        for (int nj = 0; nj < 4; nj++) {
            float* A = acc[mi * 4 + nj];
            int r  = wm * 64 + mi * 16 + (lane >> 2);
            int cc = wn * 32 + nj * 8 + 2 * (lane & 3);
            *(float2*)(obase + (size_t)r * TDIM + cc)       = make_float2(A[0], A[1]);
            *(float2*)(obase + (size_t)(r + 8) * TDIM + cc) = make_float2(A[2], A[3]);
        }
    }

    // ---- fused argmax partial over this CTA's 128 rows ----
    float mv[8]; int mi_[8];
    #pragma unroll
    for (int nj = 0; nj < 4; nj++) {
        #pragma unroll
        for (int cc = 0; cc < 2; cc++) {
            int key = nj * 2 + cc;
            float best = -INFINITY; int bidx = 0;
            #pragma unroll
            for (int mi = 0; mi < 4; mi++) {
                #pragma unroll
                for (int hf = 0; hf < 2; hf++) {
                    float v = acc[mi * 4 + nj][hf * 2 + cc];
                    int   ix = nBase + wm * 64 + mi * 16 + (lane >> 2) + hf * 8;
                    if (v > best || (v == best && ix < bidx)) { best = v; bidx = ix; }
                }
            }
            mv[key] = best; mi_[key] = bidx;
        }
    }
    #pragma unroll
    for (int off = 4; off < 32; off <<= 1) {
        #pragma unroll
        for (int key = 0; key < 8; key++) {
            float ov = __shfl_xor_sync(0xffffffff, mv[key], off);
            int   oi = __shfl_xor_sync(0xffffffff, mi_[key], off);
            if (ov > mv[key] || (ov == mv[key] && oi < mi_[key])) {
                mv[key] = ov; mi_[key] = oi;
            }
        }
    }
    float* sval = (float*)smem;               // [2][128]
    int*   sidx = (int*)(smem + 2 * 128 * 4); // [2][128]
    if (lane < 4) {
        #pragma unroll
        for (int nj = 0; nj < 4; nj++)
            #pragma unroll
            for (int cc = 0; cc < 2; cc++) {
                int col = wn * 32 + nj * 8 + 2 * lane + cc;
                sval[wm * 128 + col] = mv[nj * 2 + cc];
                sidx[wm * 128 + col] = mi_[nj * 2 + cc];
            }
    }
    __syncthreads();
    if (tid < 128) {
        float v0 = sval[tid],      v1 = sval[128 + tid];
        int   i0 = sidx[tid],      i1 = sidx[128 + tid];
        bool take1 = (v1 > v0) || (v1 == v0 && i1 < i0);
        size_t o = ((size_t)blockIdx.y * BATCH + b) * TDIM + tBase + tid;
        g_pmax[o] = take1 ? v1 : v0;
        g_pidx[o] = take1 ? i1 : i0;
    }
}

// ------ fused final argmax (32 slices) + smem-staged z_q gather -------------
#define ZQ_PITCH 517
#define ZQ_SMEM  (32 * ZQ_PITCH * 4)     // 66176 B

__global__ void argmax_zq_kernel(float* __restrict__ idx_out, float* __restrict__ zq) {
    extern __shared__ float sV[];            // [32][ZQ_PITCH]
    __shared__ int sIdx[32];
    int b = blockIdx.y;
    int t0 = blockIdx.x * 32;
    int lane = threadIdx.x & 31;
    int wid  = threadIdx.x >> 5;

    if (threadIdx.x < 32) {
        int t = t0 + threadIdx.x;
        float best = -INFINITY; int bi = 0x7fffffff;
        #pragma unroll
        for (int z = 0; z < NBLOCKS; z++) {
            float x = g_pmax[((size_t)z * BATCH + b) * TDIM + t];
            int  ii = g_pidx[((size_t)z * BATCH + b) * TDIM + t];
            if (x > best || (x == best && ii < bi)) { best = x; bi = ii; }
        }
        g_idx[b * TDIM + t] = bi;
        sIdx[threadIdx.x] = bi;
        idx_out[b * TDIM + t] = (float)bi;
    }
    __syncthreads();

    // Phase B: each warp stages 4 rows (t-local = wid, wid+8, wid+16, wid+24)
    #pragma unroll
    for (int r4 = 0; r4 < 4; r4++) {
        int tl = wid + r4 * 8;
        const float* v = g_V + (size_t)sIdx[tl] * CDIM;
        #pragma unroll
        for (int k = 0; k < CDIM / 32; k++)
            sV[tl * ZQ_PITCH + k * 32 + lane] = __ldg(&v[k * 32 + lane]);
    }
    __syncthreads();

    // Phase C: cgrp covers 64 c's; lanes give consecutive t -> 128B stores.
    int cgrp = wid;
    float* o = zq + (size_t)b * CDIM * TDIM + t0 + lane;
    int c0 = cgrp * 64;
    #pragma unroll 8
    for (int c = c0; c < c0 + 64; c++)
        o[(size_t)c * TDIM] = sV[lane * ZQ_PITCH + c];
}

// ---------------- launcher --------------------------------------------------
extern "C" void kernel_launch(void* const* d_in, const int* in_sizes, int n_in,
                              void* d_out, int out_size) {
    const float* hidden = (const float*)d_in[0];  // [B,C,T]
    const float* cb     = (const float*)d_in[1];  // [N,C]
    const float* Wq = (const float*)d_in[2]; const float* bq = (const float*)d_in[3];
    const float* Wk = (const float*)d_in[4]; const float* bk = (const float*)d_in[5];
    const float* Wv = (const float*)d_in[6]; const float* bv = (const float*)d_in[7];
    const float* Wp = (const float*)d_in[8]; const float* bp = (const float*)d_in[9];

    float* out        = (float*)d_out;
    float* out_logits = out;                                       // B*N*T
    float* out_idx    = out + (size_t)BATCH * NCB * TDIM;          // B*T
    float* out_zq     = out_idx + (size_t)BATCH * TDIM;            // B*C*T

    cudaFuncSetAttribute(gemm_proj_all,
                         cudaFuncAttributeMaxDynamicSharedMemorySize, GEMM_SMEM);
    cudaFuncSetAttribute(gemm_logits_mma,
                         cudaFuncAttributeMaxDynamicSharedMemorySize, GEMM_SMEM);
    cudaFuncSetAttribute(argmax_zq_kernel,
                         cudaFuncAttributeMaxDynamicSharedMemorySize, ZQ_SMEM);

    // all prep (cb split, W splits, hidden split quartered + cg partials)
    prep_all_kernel<<<3840, 256>>>(cb, Wq, Wk, Wv, hidden, Wp);
    // all projections in one launch (tile 128x128)
    gemm_proj_all<<<dim3(4, 128), 256, GEMM_SMEM>>>(bq, bk, bv, bp);
    // logits + fused argmax partials
    gemm_logits_mma<<<dim3(TDIM / 128, NCB / 128, BATCH), 256, GEMM_SMEM>>>(out_logits);
    // fused final argmax + smem-staged z_q gather
    argmax_zq_kernel<<<dim3(TDIM / 32, BATCH), 256, ZQ_SMEM>>>(out_idx, out_zq);
}